// round 3
// baseline (speedup 1.0000x reference)
#include <cuda_runtime.h>
#include <cuda_bf16.h>
#include <math.h>

#define B_TOT   32768
#define OBS_DIM 256
#define HID     64
#define FEAT    128
#define N_OPT   8
#define ACT_N   18
#define TB      64

typedef unsigned long long ull;

// ---------------- scratch (no allocation allowed) ----------------
__device__ float g_state[B_TOT * FEAT];
__device__ int   g_perm[B_TOT];
__device__ int   g_counts[N_OPT];
__device__ int   g_cursor[N_OPT];

// ---------------- packed f32x2 helpers ----------------
__device__ __forceinline__ ull ffma2(ull a, ull b, ull c) {
    ull d;
    asm("fma.rn.f32x2 %0, %1, %2, %3;" : "=l"(d) : "l"(a), "l"(b), "l"(c));
    return d;
}
__device__ __forceinline__ float f2sum(ull v) {
    float lo, hi;
    asm("mov.b64 {%0,%1}, %2;" : "=f"(lo), "=f"(hi) : "l"(v));
    return lo + hi;
}
__device__ __forceinline__ ull lds2(const float* p) {
    return *reinterpret_cast<const ull*>(p);
}

__device__ __forceinline__ float wred_sum(float v) {
#pragma unroll
    for (int o = 16; o; o >>= 1) v += __shfl_xor_sync(0xffffffffu, v, o);
    return v;
}
__device__ __forceinline__ float wred_max(float v) {
#pragma unroll
    for (int o = 16; o; o >>= 1) v = fmaxf(v, __shfl_xor_sync(0xffffffffu, v, o));
    return v;
}

// =====================================================================
// Kernel 1: trunk GEMMs + heads + option histogram
// smem: s_state[64*130]=8320 | bufW[64*66]=4224 | bufB[64*66]=4224
// =====================================================================
__global__ void __launch_bounds__(256, 3) trunk_kernel(
    const float* __restrict__ obs, const int* __restrict__ opt,
    const float* __restrict__ fW1, const float* __restrict__ fb1,
    const float* __restrict__ fW2, const float* __restrict__ fb2,
    const float* __restrict__ pW,  const float* __restrict__ pb,
    const float* __restrict__ tW,  const float* __restrict__ tb,
    float* __restrict__ out_opt, float* __restrict__ out_term)
{
    extern __shared__ float sm[];
    float* s_state = sm;            // 8320
    float* bufW    = sm + 8320;     // 4224
    float* bufB    = sm + 12544;    // 4224
    __shared__ int s_cnt[N_OPT];

    const int tid = threadIdx.x;
    const int r0  = blockIdx.x * TB;
    if (tid < N_OPT) s_cnt[tid] = 0;

    const int tr = tid & 15;   // rows tr + 16*i
    const int tc = tid >> 4;   // cols tc + 16*j

    // ---------- phase 1: h = relu(obs @ fW1^T + fb1)  (M=64,N=64,K=256) ----------
    ull acc[4][4];
#pragma unroll
    for (int i = 0; i < 4; i++)
#pragma unroll
        for (int j = 0; j < 4; j++) acc[i][j] = 0ull;

    for (int kc = 0; kc < OBS_DIM; kc += 64) {
#pragma unroll
        for (int it = 0; it < 8; it++) {
            int e = tid + it * 256;              // 2048 float2 slots
            int row = e >> 5, kk = (e & 31) << 1;
            *(float2*)(bufB + row * 66 + kk) =
                *(const float2*)(obs + (r0 + row) * OBS_DIM + kc + kk);
            *(float2*)(bufW + row * 66 + kk) =
                *(const float2*)(fW1 + row * OBS_DIM + kc + kk);
        }
        __syncthreads();
#pragma unroll 8
        for (int k = 0; k < 64; k += 2) {
            ull a[4], b[4];
#pragma unroll
            for (int i = 0; i < 4; i++) a[i] = lds2(bufB + (tr + 16 * i) * 66 + k);
#pragma unroll
            for (int j = 0; j < 4; j++) b[j] = lds2(bufW + (tc + 16 * j) * 66 + k);
#pragma unroll
            for (int i = 0; i < 4; i++)
#pragma unroll
                for (int j = 0; j < 4; j++) acc[i][j] = ffma2(a[i], b[j], acc[i][j]);
        }
        __syncthreads();
    }
    // h -> bufB [64][66]
#pragma unroll
    for (int i = 0; i < 4; i++)
#pragma unroll
        for (int j = 0; j < 4; j++)
            bufB[(tr + 16 * i) * 66 + tc + 16 * j] =
                fmaxf(f2sum(acc[i][j]) + fb1[tc + 16 * j], 0.f);

    // ---------- phase 2: state = relu(h @ fW2^T + fb2) in two 64-col halves ----------
#pragma unroll
    for (int nh = 0; nh < 2; nh++) {
        // stage fW2 half: rows nh*64 .. nh*64+63, each 64 floats
#pragma unroll
        for (int it = 0; it < 8; it++) {
            int e = tid + it * 256;              // 2048 float2 slots
            int c = e >> 5, kk = (e & 31) << 1;
            *(float2*)(bufW + c * 66 + kk) =
                *(const float2*)(fW2 + (nh * 64 + c) * HID + kk);
        }
        __syncthreads();

        ull acc2[4][4];
#pragma unroll
        for (int i = 0; i < 4; i++)
#pragma unroll
            for (int j = 0; j < 4; j++) acc2[i][j] = 0ull;
#pragma unroll 8
        for (int k = 0; k < 64; k += 2) {
            ull a[4], b[4];
#pragma unroll
            for (int i = 0; i < 4; i++) a[i] = lds2(bufB + (tr + 16 * i) * 66 + k);
#pragma unroll
            for (int j = 0; j < 4; j++) b[j] = lds2(bufW + (tc + 16 * j) * 66 + k);
#pragma unroll
            for (int i = 0; i < 4; i++)
#pragma unroll
                for (int j = 0; j < 4; j++) acc2[i][j] = ffma2(a[i], b[j], acc2[i][j]);
        }
#pragma unroll
        for (int i = 0; i < 4; i++)
#pragma unroll
            for (int j = 0; j < 4; j++) {
                int cc = nh * 64 + tc + 16 * j;
                s_state[(tr + 16 * i) * 130 + cc] =
                    fmaxf(f2sum(acc2[i][j]) + fb2[cc], 0.f);
            }
        __syncthreads();
    }

    // copy state to global (coalesced, float2)
#pragma unroll
    for (int it = 0; it < 16; it++) {
        int e = tid + it * 256;                  // 4096 float2 slots
        int row = e >> 6, f2i = (e & 63) << 1;
        *(float2*)(g_state + (r0 + row) * FEAT + f2i) =
            *(const float2*)(s_state + row * 130 + f2i);
    }

    // ---------- heads: warp per row ----------
    const int w = tid >> 5, lane = tid & 31;
#pragma unroll
    for (int q = 0; q < 8; q++) {
        int r = w * 8 + q;
        int gi = r0 + r;
        int o = opt[gi];
        ull pv = 0ull, tv = 0ull;
#pragma unroll
        for (int j = 0; j < 2; j++) {
            ull sv = lds2(s_state + r * 130 + 4 * lane + 2 * j);
            pv = ffma2(sv, *(const ull*)(pW + o * FEAT + 4 * lane + 2 * j), pv);
            tv = ffma2(sv, *(const ull*)(tW + o * FEAT + 4 * lane + 2 * j), tv);
        }
        float pvs = wred_sum(f2sum(pv));
        float tvs = wred_sum(f2sum(tv));
        if (lane == 0) {
            out_opt[gi]  = pvs + pb[o];
            out_term[gi] = 1.f / (1.f + expf(-(tvs + tb[o])));
        }
    }

    // ---------- histogram ----------
    if (tid < TB) atomicAdd(&s_cnt[opt[r0 + tid]], 1);
    __syncthreads();
    if (tid < N_OPT && s_cnt[tid]) atomicAdd(&g_counts[tid], s_cnt[tid]);
}

// =====================================================================
__global__ void scan_kernel()
{
    if (threadIdx.x == 0) {
        int s = 0;
#pragma unroll
        for (int i = 0; i < N_OPT; i++) {
            int c = g_counts[i];
            g_cursor[i] = s;
            s += c;
            g_counts[i] = 0;
        }
    }
}

__global__ void scatter_kernel(const int* __restrict__ opt)
{
    __shared__ int s_c[N_OPT];
    __shared__ int s_base[N_OPT];
    int t = threadIdx.x;
    if (t < N_OPT) s_c[t] = 0;
    __syncthreads();
    int i = blockIdx.x * blockDim.x + t;
    int o = opt[i];
    int loc = atomicAdd(&s_c[o], 1);
    __syncthreads();
    if (t < N_OPT) s_base[t] = atomicAdd(&g_cursor[t], s_c[t]);
    __syncthreads();
    g_perm[s_base[o] + loc] = i;
}

// =====================================================================
// Kernel 4: expert MLP on option-sorted tiles, fused logits+log-softmax
// smem: s_st[64*130]=8320 | s_wh[64*66]=4224 | s_eh[64*66]=4224 | s_w2[18*66]=1188
// =====================================================================
__global__ void __launch_bounds__(256, 3) expert_kernel(
    const float* __restrict__ oW1, const float* __restrict__ ob1,
    const float* __restrict__ oW2, const float* __restrict__ ob2,
    const int* __restrict__ opt, const int* __restrict__ act,
    float* __restrict__ out_logp)
{
    extern __shared__ float sm[];
    float* s_st = sm;              // 8320
    float* s_wh = sm + 8320;       // 4224
    float* s_eh = sm + 12544;      // 4224
    float* s_w2 = sm + 16768;      // 1188
    __shared__ int s_idx[TB];
    __shared__ int s_opt[TB];

    const int tid = threadIdx.x;
    const int r0  = blockIdx.x * TB;
    const int w = tid >> 5, lane = tid & 31;

    if (tid < TB) {
        int gi = g_perm[r0 + tid];
        s_idx[tid] = gi;
        s_opt[tid] = opt[gi];
    }
    __syncthreads();
#pragma unroll
    for (int it = 0; it < 16; it++) {
        int e = tid + it * 256;                  // 4096 float2 slots
        int row = e >> 6, f2i = (e & 63) << 1;
        *(float2*)(s_st + row * 130 + f2i) =
            *(const float2*)(g_state + s_idx[row] * FEAT + f2i);
    }
    __syncthreads();

    const int tr = tid & 15, tc = tid >> 4;

    int j = 0;
    while (j < TB) {
        const int o = s_opt[j];
        int re = j + 1;
        while (re < TB && s_opt[re] == o) re++;

        // stage oW2[o] [18][64] -> s_w2
#pragma unroll
        for (int it = 0; it < 3; it++) {
            int e = tid + it * 256;              // 576 float2 slots
            if (e < ACT_N * 32) {
                int a = e >> 5, h2 = (e & 31) << 1;
                *(float2*)(s_w2 + a * 66 + h2) =
                    *(const float2*)(oW2 + o * ACT_N * HID + a * HID + h2);
            }
        }

        // eh = relu(state @ W1^T + b1), K split in two 64-halves
        ull acc[4][4];
#pragma unroll
        for (int i = 0; i < 4; i++)
#pragma unroll
            for (int q = 0; q < 4; q++) acc[i][q] = 0ull;

#pragma unroll
        for (int kh = 0; kh < 2; kh++) {
            // stage W1 half: s_wh[h][k] = oW1[o][h][kh*64+k]
#pragma unroll
            for (int it = 0; it < 8; it++) {
                int e = tid + it * 256;          // 2048 float2 slots
                int h = e >> 5, kk = (e & 31) << 1;
                *(float2*)(s_wh + h * 66 + kk) =
                    *(const float2*)(oW1 + (o * HID + h) * FEAT + kh * 64 + kk);
            }
            __syncthreads();
#pragma unroll 8
            for (int k = 0; k < 64; k += 2) {
                ull a[4], b[4];
#pragma unroll
                for (int i = 0; i < 4; i++)
                    a[i] = lds2(s_st + (tr + 16 * i) * 130 + kh * 64 + k);
#pragma unroll
                for (int q = 0; q < 4; q++)
                    b[q] = lds2(s_wh + (tc + 16 * q) * 66 + k);
#pragma unroll
                for (int i = 0; i < 4; i++)
#pragma unroll
                    for (int q = 0; q < 4; q++) acc[i][q] = ffma2(a[i], b[q], acc[i][q]);
            }
            __syncthreads();
        }
#pragma unroll
        for (int i = 0; i < 4; i++) {
            int rr = tr + 16 * i;
            if (rr >= j && rr < re) {
#pragma unroll
                for (int q = 0; q < 4; q++) {
                    int cc = tc + 16 * q;
                    s_eh[rr * 66 + cc] =
                        fmaxf(f2sum(acc[i][q]) + ob1[o * HID + cc], 0.f);
                }
            }
        }
        __syncthreads();

        // fused logits + log-softmax: warp per row, lane = action
        for (int r = j + w; r < re; r += 8) {
            float v = -INFINITY;
            if (lane < ACT_N) {
                ull s0 = 0ull, s1 = 0ull;
#pragma unroll
                for (int h = 0; h < HID; h += 4) {
                    s0 = ffma2(lds2(s_eh + r * 66 + h),     lds2(s_w2 + lane * 66 + h),     s0);
                    s1 = ffma2(lds2(s_eh + r * 66 + h + 2), lds2(s_w2 + lane * 66 + h + 2), s1);
                }
                v = f2sum(s0) + f2sum(s1) + ob2[o * ACT_N + lane];
            }
            float m = wred_max(v);
            float ex = (lane < ACT_N) ? expf(v - m) : 0.f;
            float S = wred_sum(ex);
            int gi = s_idx[r];
            int a  = act[gi];
            float va = __shfl_sync(0xffffffffu, v, a);
            if (lane == 0) out_logp[gi] = va - m - logf(S);
        }
        __syncthreads();   // protect s_eh/s_w2/s_wh before next run
        j = re;
    }
}

// =====================================================================
extern "C" void kernel_launch(void* const* d_in, const int* in_sizes, int n_in,
                              void* d_out, int out_size)
{
    const float* obs = (const float*)d_in[0];
    const int*   act = (const int*)  d_in[1];
    const int*   opt = (const int*)  d_in[2];
    const float* fW1 = (const float*)d_in[3];
    const float* fb1 = (const float*)d_in[4];
    const float* fW2 = (const float*)d_in[5];
    const float* fb2 = (const float*)d_in[6];
    const float* pW  = (const float*)d_in[7];
    const float* pb  = (const float*)d_in[8];
    const float* tW  = (const float*)d_in[9];
    const float* tb  = (const float*)d_in[10];
    const float* oW1 = (const float*)d_in[11];
    const float* ob1 = (const float*)d_in[12];
    const float* oW2 = (const float*)d_in[13];
    const float* ob2 = (const float*)d_in[14];

    float* out_logp = (float*)d_out;
    float* out_opt  = out_logp + B_TOT;
    float* out_term = out_logp + 2 * B_TOT;

    const int smem1 = 16768 * (int)sizeof(float);   // 67,072 B
    const int smem4 = 17956 * (int)sizeof(float);   // 71,824 B
    cudaFuncSetAttribute(trunk_kernel,  cudaFuncAttributeMaxDynamicSharedMemorySize, smem1);
    cudaFuncSetAttribute(expert_kernel, cudaFuncAttributeMaxDynamicSharedMemorySize, smem4);

    trunk_kernel<<<B_TOT / TB, 256, smem1>>>(obs, opt, fW1, fb1, fW2, fb2,
                                             pW, pb, tW, tb, out_opt, out_term);
    scan_kernel<<<1, 32>>>();
    scatter_kernel<<<B_TOT / 256, 256>>>(opt);
    expert_kernel<<<B_TOT / TB, 256, smem4>>>(oW1, ob1, oW2, ob2, opt, act, out_logp);
}

// round 4
// speedup vs baseline: 1.3359x; 1.3359x over previous
#include <cuda_runtime.h>
#include <cuda_bf16.h>
#include <math.h>

#define B_TOT   32768
#define OBS_DIM 256
#define HID     64
#define FEAT    128
#define N_OPT   8
#define ACT_N   18
#define TB      64

typedef unsigned long long ull;

// ---------------- scratch (no allocation allowed) ----------------
__device__ float g_state[B_TOT * FEAT];
__device__ int   g_perm[B_TOT];
__device__ int   g_counts[N_OPT];
__device__ int   g_cursor[N_OPT];

// ---------------- packed f32x2 helpers (kept for logits/heads) ----------------
__device__ __forceinline__ ull ffma2(ull a, ull b, ull c) {
    ull d;
    asm("fma.rn.f32x2 %0, %1, %2, %3;" : "=l"(d) : "l"(a), "l"(b), "l"(c));
    return d;
}
__device__ __forceinline__ float f2sum(ull v) {
    float lo, hi;
    asm("mov.b64 {%0,%1}, %2;" : "=f"(lo), "=f"(hi) : "l"(v));
    return lo + hi;
}
__device__ __forceinline__ ull lds2(const float* p) {
    return *reinterpret_cast<const ull*>(p);
}
__device__ __forceinline__ float wred_sum(float v) {
#pragma unroll
    for (int o = 16; o; o >>= 1) v += __shfl_xor_sync(0xffffffffu, v, o);
    return v;
}
__device__ __forceinline__ float wred_max(float v) {
#pragma unroll
    for (int o = 16; o; o >>= 1) v = fmaxf(v, __shfl_xor_sync(0xffffffffu, v, o));
    return v;
}

// ---------------- bf16x3 helpers ----------------
// split two f32 into packed bf16x2 hi and lo (x -> low half, y -> high half)
__device__ __forceinline__ void split2(float x, float y, unsigned& hi, unsigned& lo) {
    __nv_bfloat162 h = __floats2bfloat162_rn(x, y);
    float hx = __bfloat162float(h.x);
    float hy = __bfloat162float(h.y);
    __nv_bfloat162 l = __floats2bfloat162_rn(x - hx, y - hy);
    hi = *reinterpret_cast<unsigned*>(&h);
    lo = *reinterpret_cast<unsigned*>(&l);
}

__device__ __forceinline__ void mma16816(float d[4], const unsigned a[4], const unsigned b[2]) {
    asm("mma.sync.aligned.m16n8k16.row.col.f32.bf16.bf16.f32 "
        "{%0,%1,%2,%3},{%4,%5,%6,%7},{%8,%9},{%0,%1,%2,%3};"
        : "+f"(d[0]), "+f"(d[1]), "+f"(d[2]), "+f"(d[3])
        : "r"(a[0]), "r"(a[1]), "r"(a[2]), "r"(a[3]), "r"(b[0]), "r"(b[1]));
}

// Warp computes a 16m x 32n tile of A[64xK] * W[64..128 n rows][K]^T with bf16x3.
// A/W stored as packed bf16x2 (u32 per k-pair), row strides sa/sw (u32 units).
__device__ __forceinline__ void warp_mma_tile(
    const unsigned* __restrict__ Ahi, const unsigned* __restrict__ Alo, int sa,
    const unsigned* __restrict__ Whi, const unsigned* __restrict__ Wlo, int sw,
    int m0, int n0, int ksteps, int lane, float acc[4][4])
{
    const int g = lane >> 2, t = lane & 3;
#pragma unroll
    for (int ks = 0; ks < 8; ks++) {
        if (ks >= ksteps) break;
        const int kp = ks * 8 + t;
        const int ra = (m0 + g) * sa + kp;
        const int rb = (m0 + g + 8) * sa + kp;
        unsigned ah[4], al[4];
        ah[0] = Ahi[ra]; ah[1] = Ahi[rb]; ah[2] = Ahi[ra + 4]; ah[3] = Ahi[rb + 4];
        al[0] = Alo[ra]; al[1] = Alo[rb]; al[2] = Alo[ra + 4]; al[3] = Alo[rb + 4];
#pragma unroll
        for (int nt = 0; nt < 4; nt++) {
            const int rw = (n0 + nt * 8 + g) * sw + kp;
            unsigned bh[2] = { Whi[rw], Whi[rw + 4] };
            unsigned bl[2] = { Wlo[rw], Wlo[rw + 4] };
            mma16816(acc[nt], ah, bh);
            mma16816(acc[nt], al, bh);
            mma16816(acc[nt], ah, bl);
        }
    }
}

// =====================================================================
// Kernel 1: trunk GEMMs (tensor core bf16x3) + heads + option histogram
// smem floats: s_state 8320 | aHi/aLo/wHi/wLo/hHi/hLo 6*2304 = 13824
// =====================================================================
__global__ void __launch_bounds__(256, 2) trunk_kernel(
    const float* __restrict__ obs, const int* __restrict__ opt,
    const float* __restrict__ fW1, const float* __restrict__ fb1,
    const float* __restrict__ fW2, const float* __restrict__ fb2,
    const float* __restrict__ pW,  const float* __restrict__ pb,
    const float* __restrict__ tW,  const float* __restrict__ tb,
    float* __restrict__ out_opt, float* __restrict__ out_term)
{
    extern __shared__ float sm[];
    float* s_state = sm;                                  // 64*130 = 8320
    unsigned* aHi = (unsigned*)(sm + 8320);               // 64*36 = 2304 each
    unsigned* aLo = aHi + 2304;
    unsigned* wHi = aHi + 4608;
    unsigned* wLo = aHi + 6912;
    unsigned* hHi = aHi + 9216;
    unsigned* hLo = aHi + 11520;
    __shared__ int s_cnt[N_OPT];

    const int tid  = threadIdx.x;
    const int r0   = blockIdx.x * TB;
    const int w    = tid >> 5, lane = tid & 31;
    const int g    = lane >> 2, t = lane & 3;
    const int m0   = (w & 3) * 16;
    const int n0   = (w >> 2) * 32;
    if (tid < N_OPT) s_cnt[tid] = 0;

    // ---------- phase 1: h = relu(obs @ fW1^T + fb1), K=256 in 4 chunks ----------
    float acc[4][4];
#pragma unroll
    for (int i = 0; i < 4; i++)
#pragma unroll
        for (int j = 0; j < 4; j++) acc[i][j] = 0.f;

    for (int kc = 0; kc < OBS_DIM; kc += 64) {
#pragma unroll
        for (int it = 0; it < 8; it++) {
            int e = tid + it * 256;               // 2048 u32 slots
            int row = e >> 5, p = e & 31;
            float2 ov = *(const float2*)(obs + (r0 + row) * OBS_DIM + kc + 2 * p);
            split2(ov.x, ov.y, aHi[row * 36 + p], aLo[row * 36 + p]);
            float2 wv = *(const float2*)(fW1 + row * OBS_DIM + kc + 2 * p);
            split2(wv.x, wv.y, wHi[row * 36 + p], wLo[row * 36 + p]);
        }
        __syncthreads();
        warp_mma_tile(aHi, aLo, 36, wHi, wLo, 36, m0, n0, 4, lane, acc);
        __syncthreads();
    }
    // epilogue -> h (bf16 hi/lo packed), rows m0+g / m0+g+8
    {
        const int r1 = m0 + g, r2 = m0 + g + 8;
#pragma unroll
        for (int nt = 0; nt < 4; nt++) {
            int c = n0 + nt * 8 + 2 * t;
            float b0 = fb1[c], b1 = fb1[c + 1];
            float v0 = fmaxf(acc[nt][0] + b0, 0.f), v1 = fmaxf(acc[nt][1] + b1, 0.f);
            split2(v0, v1, hHi[r1 * 36 + (c >> 1)], hLo[r1 * 36 + (c >> 1)]);
            float v2 = fmaxf(acc[nt][2] + b0, 0.f), v3 = fmaxf(acc[nt][3] + b1, 0.f);
            split2(v2, v3, hHi[r2 * 36 + (c >> 1)], hLo[r2 * 36 + (c >> 1)]);
        }
    }

    // ---------- phase 2: state = relu(h @ fW2^T + fb2), N=128 in 2 halves ----------
#pragma unroll
    for (int nh = 0; nh < 2; nh++) {
#pragma unroll
        for (int it = 0; it < 8; it++) {
            int e = tid + it * 256;               // 2048 u32 slots
            int c = e >> 5, p = e & 31;
            float2 wv = *(const float2*)(fW2 + (nh * 64 + c) * HID + 2 * p);
            split2(wv.x, wv.y, wHi[c * 36 + p], wLo[c * 36 + p]);
        }
        __syncthreads();
        float acc2[4][4];
#pragma unroll
        for (int i = 0; i < 4; i++)
#pragma unroll
            for (int j = 0; j < 4; j++) acc2[i][j] = 0.f;
        warp_mma_tile(hHi, hLo, 36, wHi, wLo, 36, m0, n0, 4, lane, acc2);
        // epilogue -> s_state (f32)
        const int r1 = m0 + g, r2 = m0 + g + 8;
#pragma unroll
        for (int nt = 0; nt < 4; nt++) {
            int c = nh * 64 + n0 + nt * 8 + 2 * t;
            float b0 = fb2[c], b1 = fb2[c + 1];
            s_state[r1 * 130 + c]     = fmaxf(acc2[nt][0] + b0, 0.f);
            s_state[r1 * 130 + c + 1] = fmaxf(acc2[nt][1] + b1, 0.f);
            s_state[r2 * 130 + c]     = fmaxf(acc2[nt][2] + b0, 0.f);
            s_state[r2 * 130 + c + 1] = fmaxf(acc2[nt][3] + b1, 0.f);
        }
        __syncthreads();
    }

    // copy state to global (coalesced, float2)
#pragma unroll
    for (int it = 0; it < 16; it++) {
        int e = tid + it * 256;
        int row = e >> 6, f2i = (e & 63) << 1;
        *(float2*)(g_state + (r0 + row) * FEAT + f2i) =
            *(const float2*)(s_state + row * 130 + f2i);
    }

    // ---------- heads: warp per row ----------
#pragma unroll
    for (int q = 0; q < 8; q++) {
        int r = w * 8 + q;
        int gi = r0 + r;
        int o = opt[gi];
        ull pv = 0ull, tv = 0ull;
#pragma unroll
        for (int j = 0; j < 2; j++) {
            ull sv = lds2(s_state + r * 130 + 4 * lane + 2 * j);
            pv = ffma2(sv, *(const ull*)(pW + o * FEAT + 4 * lane + 2 * j), pv);
            tv = ffma2(sv, *(const ull*)(tW + o * FEAT + 4 * lane + 2 * j), tv);
        }
        float pvs = wred_sum(f2sum(pv));
        float tvs = wred_sum(f2sum(tv));
        if (lane == 0) {
            out_opt[gi]  = pvs + pb[o];
            out_term[gi] = 1.f / (1.f + expf(-(tvs + tb[o])));
        }
    }

    // ---------- histogram ----------
    if (tid < TB) atomicAdd(&s_cnt[opt[r0 + tid]], 1);
    __syncthreads();
    if (tid < N_OPT && s_cnt[tid]) atomicAdd(&g_counts[tid], s_cnt[tid]);
}

// =====================================================================
__global__ void scan_kernel()
{
    if (threadIdx.x == 0) {
        int s = 0;
#pragma unroll
        for (int i = 0; i < N_OPT; i++) {
            int c = g_counts[i];
            g_cursor[i] = s;
            s += c;
            g_counts[i] = 0;
        }
    }
}

__global__ void scatter_kernel(const int* __restrict__ opt)
{
    __shared__ int s_c[N_OPT];
    __shared__ int s_base[N_OPT];
    int t = threadIdx.x;
    if (t < N_OPT) s_c[t] = 0;
    __syncthreads();
    int i = blockIdx.x * blockDim.x + t;
    int o = opt[i];
    int loc = atomicAdd(&s_c[o], 1);
    __syncthreads();
    if (t < N_OPT) s_base[t] = atomicAdd(&g_cursor[t], s_c[t]);
    __syncthreads();
    g_perm[s_base[o] + loc] = i;
}

// =====================================================================
// Kernel 4: expert MLP (tensor core bf16x3) + fused logits/log-softmax
// smem u32: stHi/stLo/wHi/wLo 4*4352 | s_eh f32 4224 | s_w2 f32 1188
// =====================================================================
__global__ void __launch_bounds__(256, 2) expert_kernel(
    const float* __restrict__ oW1, const float* __restrict__ ob1,
    const float* __restrict__ oW2, const float* __restrict__ ob2,
    const int* __restrict__ opt, const int* __restrict__ act,
    float* __restrict__ out_logp)
{
    extern __shared__ float sm[];
    unsigned* stHi = (unsigned*)sm;            // 64*68 = 4352 each
    unsigned* stLo = stHi + 4352;
    unsigned* wHi  = stHi + 8704;
    unsigned* wLo  = stHi + 13056;
    float* s_eh = (float*)(stHi + 17408);      // 64*66 = 4224
    float* s_w2 = s_eh + 4224;                 // 18*66 = 1188
    __shared__ int s_idx[TB];
    __shared__ int s_opt[TB];

    const int tid  = threadIdx.x;
    const int r0   = blockIdx.x * TB;
    const int w    = tid >> 5, lane = tid & 31;
    const int g    = lane >> 2, t = lane & 3;
    const int m0   = (w & 3) * 16;
    const int n0   = (w >> 2) * 32;

    if (tid < TB) {
        int gi = g_perm[r0 + tid];
        s_idx[tid] = gi;
        s_opt[tid] = opt[gi];
    }
    __syncthreads();
    // stage state rows (gathered) as bf16 hi/lo
#pragma unroll
    for (int it = 0; it < 16; it++) {
        int e = tid + it * 256;                // 4096 u32 slots
        int row = e >> 6, p = e & 63;
        float2 v = *(const float2*)(g_state + s_idx[row] * FEAT + 2 * p);
        split2(v.x, v.y, stHi[row * 68 + p], stLo[row * 68 + p]);
    }
    __syncthreads();

    int j = 0;
    while (j < TB) {
        const int o = s_opt[j];
        int re = j + 1;
        while (re < TB && s_opt[re] == o) re++;

        // stage oW1[o] as bf16 hi/lo, oW2[o] as f32
#pragma unroll
        for (int it = 0; it < 16; it++) {
            int e = tid + it * 256;
            int h = e >> 6, p = e & 63;
            float2 v = *(const float2*)(oW1 + (o * HID + h) * FEAT + 2 * p);
            split2(v.x, v.y, wHi[h * 68 + p], wLo[h * 68 + p]);
        }
#pragma unroll
        for (int it = 0; it < 3; it++) {
            int e = tid + it * 256;            // 576 float2 slots
            if (e < ACT_N * 32) {
                int a = e >> 5, h2 = (e & 31) << 1;
                *(float2*)(s_w2 + a * 66 + h2) =
                    *(const float2*)(oW2 + o * ACT_N * HID + a * HID + h2);
            }
        }
        __syncthreads();

        // eh = relu(state @ W1^T + b1) via bf16x3 MMA, K=128 (8 k-steps)
        float acc[4][4];
#pragma unroll
        for (int i = 0; i < 4; i++)
#pragma unroll
            for (int q = 0; q < 4; q++) acc[i][q] = 0.f;
        warp_mma_tile(stHi, stLo, 68, wHi, wLo, 68, m0, n0, 8, lane, acc);

        // guarded epilogue -> s_eh (only rows in [j, re))
        {
            const int r1 = m0 + g, r2 = m0 + g + 8;
#pragma unroll
            for (int nt = 0; nt < 4; nt++) {
                int c = n0 + nt * 8 + 2 * t;
                float b0 = ob1[o * HID + c], b1 = ob1[o * HID + c + 1];
                if (r1 >= j && r1 < re) {
                    s_eh[r1 * 66 + c]     = fmaxf(acc[nt][0] + b0, 0.f);
                    s_eh[r1 * 66 + c + 1] = fmaxf(acc[nt][1] + b1, 0.f);
                }
                if (r2 >= j && r2 < re) {
                    s_eh[r2 * 66 + c]     = fmaxf(acc[nt][2] + b0, 0.f);
                    s_eh[r2 * 66 + c + 1] = fmaxf(acc[nt][3] + b1, 0.f);
                }
            }
        }
        __syncthreads();

        // fused logits + log-softmax: warp per row, lane = action
        for (int r = j + w; r < re; r += 8) {
            float v = -INFINITY;
            if (lane < ACT_N) {
                ull s0 = 0ull, s1 = 0ull;
#pragma unroll
                for (int h = 0; h < HID; h += 4) {
                    s0 = ffma2(lds2(s_eh + r * 66 + h),     lds2(s_w2 + lane * 66 + h),     s0);
                    s1 = ffma2(lds2(s_eh + r * 66 + h + 2), lds2(s_w2 + lane * 66 + h + 2), s1);
                }
                v = f2sum(s0) + f2sum(s1) + ob2[o * ACT_N + lane];
            }
            float m = wred_max(v);
            float ex = (lane < ACT_N) ? expf(v - m) : 0.f;
            float S = wred_sum(ex);
            int gi = s_idx[r];
            int a  = act[gi];
            float va = __shfl_sync(0xffffffffu, v, a);
            if (lane == 0) out_logp[gi] = va - m - logf(S);
        }
        __syncthreads();
        j = re;
    }
}

// =====================================================================
extern "C" void kernel_launch(void* const* d_in, const int* in_sizes, int n_in,
                              void* d_out, int out_size)
{
    const float* obs = (const float*)d_in[0];
    const int*   act = (const int*)  d_in[1];
    const int*   opt = (const int*)  d_in[2];
    const float* fW1 = (const float*)d_in[3];
    const float* fb1 = (const float*)d_in[4];
    const float* fW2 = (const float*)d_in[5];
    const float* fb2 = (const float*)d_in[6];
    const float* pW  = (const float*)d_in[7];
    const float* pb  = (const float*)d_in[8];
    const float* tW  = (const float*)d_in[9];
    const float* tb  = (const float*)d_in[10];
    const float* oW1 = (const float*)d_in[11];
    const float* ob1 = (const float*)d_in[12];
    const float* oW2 = (const float*)d_in[13];
    const float* ob2 = (const float*)d_in[14];

    float* out_logp = (float*)d_out;
    float* out_opt  = out_logp + B_TOT;
    float* out_term = out_logp + 2 * B_TOT;

    const int smem1 = (8320 + 6 * 2304) * (int)sizeof(float);       // 88,576 B
    const int smem4 = (4 * 4352 + 4224 + 1188) * (int)sizeof(float); // 91,280 B
    cudaFuncSetAttribute(trunk_kernel,  cudaFuncAttributeMaxDynamicSharedMemorySize, smem1);
    cudaFuncSetAttribute(expert_kernel, cudaFuncAttributeMaxDynamicSharedMemorySize, smem4);

    trunk_kernel<<<B_TOT / TB, 256, smem1>>>(obs, opt, fW1, fb1, fW2, fb2,
                                             pW, pb, tW, tb, out_opt, out_term);
    scan_kernel<<<1, 32>>>();
    scatter_kernel<<<B_TOT / 256, 256>>>(opt);
    expert_kernel<<<B_TOT / TB, 256, smem4>>>(oW1, ob1, oW2, ob2, opt, act, out_logp);
}

// round 5
// speedup vs baseline: 1.4448x; 1.0815x over previous
#include <cuda_runtime.h>
#include <cuda_bf16.h>
#include <math.h>

#define B_TOT   32768
#define OBS_DIM 256
#define HID     64
#define FEAT    128
#define N_OPT   8
#define ACT_N   18
#define TB      64

typedef unsigned long long ull;
typedef unsigned u32;

// ---------------- scratch (no allocation allowed) ----------------
__device__ u32  g_stateh[B_TOT * 64];   // state as packed bf16x2 hi
__device__ u32  g_statel[B_TOT * 64];   // state as packed bf16x2 lo
__device__ int  g_perm[B_TOT];
__device__ int  g_counts[N_OPT];
__device__ int  g_cursor[N_OPT];
// pre-split weights (packed bf16x2 along K)
__device__ u32  d_fW1h[64 * 128],  d_fW1l[64 * 128];   // [hid][k/2] K=256
__device__ u32  d_fW2h[128 * 32],  d_fW2l[128 * 32];   // [feat][k/2] K=64
__device__ u32  d_oW1h[8 * 64 * 64], d_oW1l[8 * 64 * 64]; // [opt][hid][k/2] K=128

// ---------------- packed f32x2 helpers ----------------
__device__ __forceinline__ ull ffma2(ull a, ull b, ull c) {
    ull d;
    asm("fma.rn.f32x2 %0, %1, %2, %3;" : "=l"(d) : "l"(a), "l"(b), "l"(c));
    return d;
}
__device__ __forceinline__ float f2sum(ull v) {
    float lo, hi;
    asm("mov.b64 {%0,%1}, %2;" : "=f"(lo), "=f"(hi) : "l"(v));
    return lo + hi;
}
__device__ __forceinline__ ull lds2(const float* p) {
    return *reinterpret_cast<const ull*>(p);
}
__device__ __forceinline__ float wred_sum(float v) {
#pragma unroll
    for (int o = 16; o; o >>= 1) v += __shfl_xor_sync(0xffffffffu, v, o);
    return v;
}
__device__ __forceinline__ float wred_max(float v) {
#pragma unroll
    for (int o = 16; o; o >>= 1) v = fmaxf(v, __shfl_xor_sync(0xffffffffu, v, o));
    return v;
}

// ---------------- bf16x3 helpers ----------------
__device__ __forceinline__ void split2(float x, float y, u32& hi, u32& lo) {
    __nv_bfloat162 h = __floats2bfloat162_rn(x, y);
    float hx = __bfloat162float(h.x);
    float hy = __bfloat162float(h.y);
    __nv_bfloat162 l = __floats2bfloat162_rn(x - hx, y - hy);
    hi = *reinterpret_cast<u32*>(&h);
    lo = *reinterpret_cast<u32*>(&l);
}

__device__ __forceinline__ void mma16816(float d[4], const u32 a[4], const u32 b[2]) {
    asm("mma.sync.aligned.m16n8k16.row.col.f32.bf16.bf16.f32 "
        "{%0,%1,%2,%3},{%4,%5,%6,%7},{%8,%9},{%0,%1,%2,%3};"
        : "+f"(d[0]), "+f"(d[1]), "+f"(d[2]), "+f"(d[3])
        : "r"(a[0]), "r"(a[1]), "r"(a[2]), "r"(a[3]), "r"(b[0]), "r"(b[1]));
}

__device__ __forceinline__ void ldsm4(u32 r[4], u32 addr) {
    asm volatile("ldmatrix.sync.aligned.m8n8.x4.shared.b16 {%0,%1,%2,%3}, [%4];"
        : "=r"(r[0]), "=r"(r[1]), "=r"(r[2]), "=r"(r[3]) : "r"(addr));
}

// Warp computes 16m x 32n of A[rows][K] * W[n rows][K]^T, bf16x3, via ldmatrix.
// sa/sw: row strides in u32. KSTEPS k16-steps.
template <int KSTEPS>
__device__ __forceinline__ void warp_mma_tile(
    const u32* Ahi, const u32* Alo, int sa,
    const u32* Whi, const u32* Wlo, int sw,
    int m0, int n0, int lane, float acc[4][4])
{
    const int mat = lane >> 3, rin = lane & 7;
    // A mats: 0: rows m0+0..7 col0 | 1: +8 col0 | 2: rows col+4 | 3: +8 col+4
    u32 aOff = (u32)(((m0 + rin + ((mat & 1) << 3)) * sa + ((mat >> 1) << 2)) << 2);
    u32 aHiA = (u32)__cvta_generic_to_shared(Ahi) + aOff;
    u32 aLoA = (u32)__cvta_generic_to_shared(Alo) + aOff;
    // B mats (per pair): 0: rows nt+0..7 col0 | 1: col+4 | 2: rows +8 col0 | 3: +8 col+4
    u32 bOff0 = (u32)(((n0 + ((mat >> 1) << 3) + rin) * sw + ((mat & 1) << 2)) << 2);
    u32 bOff1 = bOff0 + (u32)(16 * sw * 4);
    u32 wHiB = (u32)__cvta_generic_to_shared(Whi);
    u32 wLoB = (u32)__cvta_generic_to_shared(Wlo);

#pragma unroll
    for (int ks = 0; ks < KSTEPS; ks++) {
        const u32 kb = ks * 32;   // 8 u32 per k16 step
        u32 ah[4], al[4], b0h[4], b1h[4], b0l[4], b1l[4];
        ldsm4(ah, aHiA + kb);
        ldsm4(al, aLoA + kb);
        ldsm4(b0h, wHiB + bOff0 + kb);
        ldsm4(b1h, wHiB + bOff1 + kb);
        ldsm4(b0l, wLoB + bOff0 + kb);
        ldsm4(b1l, wLoB + bOff1 + kb);
        mma16816(acc[0], ah, b0h + 0);
        mma16816(acc[1], ah, b0h + 2);
        mma16816(acc[2], ah, b1h + 0);
        mma16816(acc[3], ah, b1h + 2);
        mma16816(acc[0], al, b0h + 0);
        mma16816(acc[1], al, b0h + 2);
        mma16816(acc[2], al, b1h + 0);
        mma16816(acc[3], al, b1h + 2);
        mma16816(acc[0], ah, b0l + 0);
        mma16816(acc[1], ah, b0l + 2);
        mma16816(acc[2], ah, b1l + 0);
        mma16816(acc[3], ah, b1l + 2);
    }
}

// =====================================================================
// Kernel 0: pre-split all reused weights into bf16 hi/lo
// =====================================================================
__global__ void split_kernel(const float* __restrict__ fW1,
                             const float* __restrict__ fW2,
                             const float* __restrict__ oW1)
{
    int i = blockIdx.x * blockDim.x + threadIdx.x;
    if (i < 8192) {
        float2 v = ((const float2*)fW1)[i];
        split2(v.x, v.y, d_fW1h[i], d_fW1l[i]);
    } else if (i < 12288) {
        int k = i - 8192;
        float2 v = ((const float2*)fW2)[k];
        split2(v.x, v.y, d_fW2h[k], d_fW2l[k]);
    } else if (i < 45056) {
        int k = i - 12288;
        float2 v = ((const float2*)oW1)[k];
        split2(v.x, v.y, d_oW1h[k], d_oW1l[k]);
    }
}

// =====================================================================
// Kernel 1: trunk GEMMs (bf16x3 MMA) + heads + histogram
// smem: s_state 8320 f32 | aHi/aLo/wH/wL/hHi/hLo 6*2304 u32
// =====================================================================
__global__ void __launch_bounds__(256, 2) trunk_kernel(
    const float* __restrict__ obs, const int* __restrict__ opt,
    const float* __restrict__ fb1, const float* __restrict__ fb2,
    const float* __restrict__ pW,  const float* __restrict__ pb,
    const float* __restrict__ tW,  const float* __restrict__ tb,
    float* __restrict__ out_opt, float* __restrict__ out_term)
{
    extern __shared__ float sm[];
    float* s_state = sm;                         // 64*130
    u32* aHi = (u32*)(sm + 8320);                // 64*36 each
    u32* aLo = aHi + 2304;
    u32* wH  = aHi + 4608;
    u32* wL  = aHi + 6912;
    u32* hHi = aHi + 9216;
    u32* hLo = aHi + 11520;
    __shared__ int s_cnt[N_OPT];

    const int tid  = threadIdx.x;
    const int r0   = blockIdx.x * TB;
    const int w    = tid >> 5, lane = tid & 31;
    const int g    = lane >> 2, t = lane & 3;
    const int m0   = (w & 3) * 16;
    const int n0   = (w >> 2) * 32;
    if (tid < N_OPT) s_cnt[tid] = 0;

    // ---------- phase 1: h = relu(obs @ fW1^T + fb1), K=256 in 4 chunks ----------
    float acc[4][4];
#pragma unroll
    for (int i = 0; i < 4; i++)
#pragma unroll
        for (int j = 0; j < 4; j++) acc[i][j] = 0.f;

    for (int kc = 0; kc < 4; kc++) {
        // obs chunk: split inline
#pragma unroll
        for (int it = 0; it < 8; it++) {
            int e = tid + it * 256;              // 2048 u32 slots
            int row = e >> 5, p = e & 31;
            float2 ov = *(const float2*)(obs + (r0 + row) * OBS_DIM + kc * 64 + 2 * p);
            split2(ov.x, ov.y, aHi[row * 36 + p], aLo[row * 36 + p]);
        }
        // fW1 chunk: plain uint4 copies of pre-split
#pragma unroll
        for (int it = 0; it < 2; it++) {
            int q = tid + it * 256;              // 512 uint4
            int row = q >> 3, p4 = (q & 7) << 2;
            *(uint4*)(wH + row * 36 + p4) = *(const uint4*)(d_fW1h + row * 128 + kc * 32 + p4);
            *(uint4*)(wL + row * 36 + p4) = *(const uint4*)(d_fW1l + row * 128 + kc * 32 + p4);
        }
        __syncthreads();
        warp_mma_tile<4>(aHi, aLo, 36, wH, wL, 36, m0, n0, lane, acc);
        __syncthreads();
    }
    // epilogue -> h (bf16 hi/lo)
    {
        const int r1 = m0 + g, r2 = m0 + g + 8;
#pragma unroll
        for (int nt = 0; nt < 4; nt++) {
            int c = n0 + nt * 8 + 2 * t;
            float b0 = fb1[c], b1 = fb1[c + 1];
            float v0 = fmaxf(acc[nt][0] + b0, 0.f), v1 = fmaxf(acc[nt][1] + b1, 0.f);
            split2(v0, v1, hHi[r1 * 36 + (c >> 1)], hLo[r1 * 36 + (c >> 1)]);
            float v2 = fmaxf(acc[nt][2] + b0, 0.f), v3 = fmaxf(acc[nt][3] + b1, 0.f);
            split2(v2, v3, hHi[r2 * 36 + (c >> 1)], hLo[r2 * 36 + (c >> 1)]);
        }
    }

    // ---------- phase 2: state = relu(h @ fW2^T + fb2), N=128 in 2 halves ----------
#pragma unroll
    for (int nh = 0; nh < 2; nh++) {
#pragma unroll
        for (int it = 0; it < 2; it++) {
            int q = tid + it * 256;              // 512 uint4
            int row = q >> 3, p4 = (q & 7) << 2;
            *(uint4*)(wH + row * 36 + p4) = *(const uint4*)(d_fW2h + (nh * 64 + row) * 32 + p4);
            *(uint4*)(wL + row * 36 + p4) = *(const uint4*)(d_fW2l + (nh * 64 + row) * 32 + p4);
        }
        __syncthreads();
        float acc2[4][4];
#pragma unroll
        for (int i = 0; i < 4; i++)
#pragma unroll
            for (int j = 0; j < 4; j++) acc2[i][j] = 0.f;
        warp_mma_tile<4>(hHi, hLo, 36, wH, wL, 36, m0, n0, lane, acc2);

        // epilogue: s_state f32 (for heads) + bf16 hi/lo direct to global
        const int r1 = m0 + g, r2 = m0 + g + 8;
#pragma unroll
        for (int nt = 0; nt < 4; nt++) {
            int c = nh * 64 + n0 + nt * 8 + 2 * t;
            float b0 = fb2[c], b1 = fb2[c + 1];
            float v0 = fmaxf(acc2[nt][0] + b0, 0.f);
            float v1 = fmaxf(acc2[nt][1] + b1, 0.f);
            float v2 = fmaxf(acc2[nt][2] + b0, 0.f);
            float v3 = fmaxf(acc2[nt][3] + b1, 0.f);
            s_state[r1 * 130 + c] = v0; s_state[r1 * 130 + c + 1] = v1;
            s_state[r2 * 130 + c] = v2; s_state[r2 * 130 + c + 1] = v3;
            u32 hi, lo;
            split2(v0, v1, hi, lo);
            g_stateh[(r0 + r1) * 64 + (c >> 1)] = hi;
            g_statel[(r0 + r1) * 64 + (c >> 1)] = lo;
            split2(v2, v3, hi, lo);
            g_stateh[(r0 + r2) * 64 + (c >> 1)] = hi;
            g_statel[(r0 + r2) * 64 + (c >> 1)] = lo;
        }
        __syncthreads();
    }

    // ---------- heads: warp per row ----------
#pragma unroll
    for (int q = 0; q < 8; q++) {
        int r = w * 8 + q;
        int gi = r0 + r;
        int o = opt[gi];
        ull pv = 0ull, tv = 0ull;
#pragma unroll
        for (int j = 0; j < 2; j++) {
            ull sv = lds2(s_state + r * 130 + 4 * lane + 2 * j);
            pv = ffma2(sv, *(const ull*)(pW + o * FEAT + 4 * lane + 2 * j), pv);
            tv = ffma2(sv, *(const ull*)(tW + o * FEAT + 4 * lane + 2 * j), tv);
        }
        float pvs = wred_sum(f2sum(pv));
        float tvs = wred_sum(f2sum(tv));
        if (lane == 0) {
            out_opt[gi]  = pvs + pb[o];
            out_term[gi] = 1.f / (1.f + expf(-(tvs + tb[o])));
        }
    }

    // ---------- histogram ----------
    if (tid < TB) atomicAdd(&s_cnt[opt[r0 + tid]], 1);
    __syncthreads();
    if (tid < N_OPT && s_cnt[tid]) atomicAdd(&g_counts[tid], s_cnt[tid]);
}

// =====================================================================
__global__ void scan_kernel()
{
    if (threadIdx.x == 0) {
        int s = 0;
#pragma unroll
        for (int i = 0; i < N_OPT; i++) {
            int c = g_counts[i];
            g_cursor[i] = s;
            s += c;
            g_counts[i] = 0;
        }
    }
}

__global__ void scatter_kernel(const int* __restrict__ opt)
{
    __shared__ int s_c[N_OPT];
    __shared__ int s_base[N_OPT];
    int t = threadIdx.x;
    if (t < N_OPT) s_c[t] = 0;
    __syncthreads();
    int i = blockIdx.x * blockDim.x + t;
    int o = opt[i];
    int loc = atomicAdd(&s_c[o], 1);
    __syncthreads();
    if (t < N_OPT) s_base[t] = atomicAdd(&g_cursor[t], s_c[t]);
    __syncthreads();
    g_perm[s_base[o] + loc] = i;
}

// =====================================================================
// Kernel 4: expert MLP (bf16x3 MMA) + fused logits/log-softmax
// smem u32: stHi 4352 | stLo 4352 | wHi 4352 (alias s_eh) | wLo 4352 (alias s_w2)
// =====================================================================
__global__ void __launch_bounds__(256, 3) expert_kernel(
    const float* __restrict__ ob1,
    const float* __restrict__ oW2, const float* __restrict__ ob2,
    const int* __restrict__ opt, const int* __restrict__ act,
    float* __restrict__ out_logp)
{
    extern __shared__ u32 smu[];
    u32* stHi = smu;                 // 64*68
    u32* stLo = smu + 4352;
    u32* wHi  = smu + 8704;
    u32* wLo  = smu + 13056;
    float* s_eh = (float*)(smu + 8704);   // alias wHi (64*66 f32, after MMA)
    float* s_w2 = (float*)(smu + 13056);  // alias wLo (18*66 f32, after MMA)
    __shared__ int s_idx[TB];
    __shared__ int s_opt[TB];

    const int tid  = threadIdx.x;
    const int r0   = blockIdx.x * TB;
    const int w    = tid >> 5, lane = tid & 31;
    const int g    = lane >> 2, t = lane & 3;
    const int m0   = (w & 3) * 16;
    const int n0   = (w >> 2) * 32;

    if (tid < TB) {
        int gi = g_perm[r0 + tid];
        s_idx[tid] = gi;
        s_opt[tid] = opt[gi];
    }
    __syncthreads();
    // gather pre-split state rows (uint4 copies)
#pragma unroll
    for (int it = 0; it < 4; it++) {
        int q = tid + it * 256;              // 1024 uint4
        int row = q >> 4, p4 = (q & 15) << 2;
        int gi = s_idx[row];
        *(uint4*)(stHi + row * 68 + p4) = *(const uint4*)(g_stateh + gi * 64 + p4);
        *(uint4*)(stLo + row * 68 + p4) = *(const uint4*)(g_statel + gi * 64 + p4);
    }
    __syncthreads();

    int j = 0;
    while (j < TB) {
        const int o = s_opt[j];
        int re = j + 1;
        while (re < TB && s_opt[re] == o) re++;

        // stage pre-split oW1[o] (uint4 copies)
#pragma unroll
        for (int it = 0; it < 4; it++) {
            int q = tid + it * 256;
            int row = q >> 4, p4 = (q & 15) << 2;
            *(uint4*)(wHi + row * 68 + p4) = *(const uint4*)(d_oW1h + (o * 64 + row) * 64 + p4);
            *(uint4*)(wLo + row * 68 + p4) = *(const uint4*)(d_oW1l + (o * 64 + row) * 64 + p4);
        }
        __syncthreads();

        // eh = relu(state @ W1^T + b1), K=128
        float acc[4][4];
#pragma unroll
        for (int i = 0; i < 4; i++)
#pragma unroll
            for (int q = 0; q < 4; q++) acc[i][q] = 0.f;
        warp_mma_tile<8>(stHi, stLo, 68, wHi, wLo, 68, m0, n0, lane, acc);
        __syncthreads();   // all warps done reading wHi/wLo before aliasing

        // guarded epilogue -> s_eh (alias wHi)
        {
            const int r1 = m0 + g, r2 = m0 + g + 8;
#pragma unroll
            for (int nt = 0; nt < 4; nt++) {
                int c = n0 + nt * 8 + 2 * t;
                float b0 = ob1[o * HID + c], b1 = ob1[o * HID + c + 1];
                if (r1 >= j && r1 < re) {
                    s_eh[r1 * 66 + c]     = fmaxf(acc[nt][0] + b0, 0.f);
                    s_eh[r1 * 66 + c + 1] = fmaxf(acc[nt][1] + b1, 0.f);
                }
                if (r2 >= j && r2 < re) {
                    s_eh[r2 * 66 + c]     = fmaxf(acc[nt][2] + b0, 0.f);
                    s_eh[r2 * 66 + c + 1] = fmaxf(acc[nt][3] + b1, 0.f);
                }
            }
        }
        // stage oW2[o] -> s_w2 (alias wLo)
#pragma unroll
        for (int it = 0; it < 3; it++) {
            int e = tid + it * 256;              // 576 float2 slots
            if (e < ACT_N * 32) {
                int a = e >> 5, h2 = (e & 31) << 1;
                *(float2*)(s_w2 + a * 66 + h2) =
                    *(const float2*)(oW2 + o * ACT_N * HID + a * HID + h2);
            }
        }
        __syncthreads();

        // fused logits + log-softmax: warp per row, lane = action
        for (int r = j + w; r < re; r += 8) {
            float v = -INFINITY;
            if (lane < ACT_N) {
                ull s0 = 0ull, s1 = 0ull;
#pragma unroll
                for (int h = 0; h < HID; h += 4) {
                    s0 = ffma2(lds2(s_eh + r * 66 + h),     lds2(s_w2 + lane * 66 + h),     s0);
                    s1 = ffma2(lds2(s_eh + r * 66 + h + 2), lds2(s_w2 + lane * 66 + h + 2), s1);
                }
                v = f2sum(s0) + f2sum(s1) + ob2[o * ACT_N + lane];
            }
            float m = wred_max(v);
            float ex = (lane < ACT_N) ? expf(v - m) : 0.f;
            float S = wred_sum(ex);
            int gi = s_idx[r];
            int a  = act[gi];
            float va = __shfl_sync(0xffffffffu, v, a);
            if (lane == 0) out_logp[gi] = va - m - logf(S);
        }
        __syncthreads();
        j = re;
    }
}

// =====================================================================
extern "C" void kernel_launch(void* const* d_in, const int* in_sizes, int n_in,
                              void* d_out, int out_size)
{
    const float* obs = (const float*)d_in[0];
    const int*   act = (const int*)  d_in[1];
    const int*   opt = (const int*)  d_in[2];
    const float* fW1 = (const float*)d_in[3];
    const float* fb1 = (const float*)d_in[4];
    const float* fW2 = (const float*)d_in[5];
    const float* fb2 = (const float*)d_in[6];
    const float* pW  = (const float*)d_in[7];
    const float* pb  = (const float*)d_in[8];
    const float* tW  = (const float*)d_in[9];
    const float* tb  = (const float*)d_in[10];
    const float* oW1 = (const float*)d_in[11];
    const float* ob1 = (const float*)d_in[12];
    const float* oW2 = (const float*)d_in[13];
    const float* ob2 = (const float*)d_in[14];

    float* out_logp = (float*)d_out;
    float* out_opt  = out_logp + B_TOT;
    float* out_term = out_logp + 2 * B_TOT;

    const int smem1 = 88576;   // trunk
    const int smem4 = 69632;   // expert
    cudaFuncSetAttribute(trunk_kernel,  cudaFuncAttributeMaxDynamicSharedMemorySize, smem1);
    cudaFuncSetAttribute(expert_kernel, cudaFuncAttributeMaxDynamicSharedMemorySize, smem4);

    split_kernel<<<176, 256>>>(fW1, fW2, oW1);
    trunk_kernel<<<B_TOT / TB, 256, smem1>>>(obs, opt, fb1, fb2,
                                             pW, pb, tW, tb, out_opt, out_term);
    scan_kernel<<<1, 32>>>();
    scatter_kernel<<<B_TOT / 256, 256>>>(opt);
    expert_kernel<<<B_TOT / TB, 256, smem4>>>(ob1, oW2, ob2, opt, act, out_logp);
}

// round 6
// speedup vs baseline: 1.6477x; 1.1404x over previous
#include <cuda_runtime.h>
#include <cuda_bf16.h>
#include <math.h>

#define B_TOT   32768
#define OBS_DIM 256
#define HID     64
#define FEAT    128
#define N_OPT   8
#define ACT_N   18
#define TB      128

typedef unsigned long long ull;
typedef unsigned u32;

// ---------------- scratch (no allocation allowed) ----------------
__device__ u32  g_stateh[B_TOT * 64];   // state packed bf16x2 hi
__device__ u32  g_statel[B_TOT * 64];   // state packed bf16x2 lo
__device__ int  g_perm[B_TOT];
__device__ int  g_counts[N_OPT];
__device__ int  g_cursor[N_OPT];
// pre-split weights (packed bf16x2 along K)
__device__ u32  d_fW1h[64 * 128],  d_fW1l[64 * 128];     // [hid][k/2] K=256
__device__ u32  d_fW2h[128 * 32],  d_fW2l[128 * 32];     // [feat][k/2] K=64
__device__ u32  d_oW1h[8 * 64 * 64], d_oW1l[8 * 64 * 64];// [opt][hid][k/2] K=128

// ---------------- packed f32x2 helpers ----------------
__device__ __forceinline__ ull ffma2(ull a, ull b, ull c) {
    ull d;
    asm("fma.rn.f32x2 %0, %1, %2, %3;" : "=l"(d) : "l"(a), "l"(b), "l"(c));
    return d;
}
__device__ __forceinline__ float f2sum(ull v) {
    float lo, hi;
    asm("mov.b64 {%0,%1}, %2;" : "=f"(lo), "=f"(hi) : "l"(v));
    return lo + hi;
}
__device__ __forceinline__ ull lds2(const float* p) {
    return *reinterpret_cast<const ull*>(p);
}
__device__ __forceinline__ float wred_sum(float v) {
#pragma unroll
    for (int o = 16; o; o >>= 1) v += __shfl_xor_sync(0xffffffffu, v, o);
    return v;
}
__device__ __forceinline__ float wred_max(float v) {
#pragma unroll
    for (int o = 16; o; o >>= 1) v = fmaxf(v, __shfl_xor_sync(0xffffffffu, v, o));
    return v;
}

// ---------------- bf16x3 helpers ----------------
__device__ __forceinline__ void split2(float x, float y, u32& hi, u32& lo) {
    __nv_bfloat162 h = __floats2bfloat162_rn(x, y);
    float hx = __bfloat162float(h.x);
    float hy = __bfloat162float(h.y);
    __nv_bfloat162 l = __floats2bfloat162_rn(x - hx, y - hy);
    hi = *reinterpret_cast<u32*>(&h);
    lo = *reinterpret_cast<u32*>(&l);
}

__device__ __forceinline__ void mma16816(float d[4], const u32 a[4], const u32 b[2]) {
    asm("mma.sync.aligned.m16n8k16.row.col.f32.bf16.bf16.f32 "
        "{%0,%1,%2,%3},{%4,%5,%6,%7},{%8,%9},{%0,%1,%2,%3};"
        : "+f"(d[0]), "+f"(d[1]), "+f"(d[2]), "+f"(d[3])
        : "r"(a[0]), "r"(a[1]), "r"(a[2]), "r"(a[3]), "r"(b[0]), "r"(b[1]));
}

__device__ __forceinline__ void ldsm4(u32 r[4], u32 addr) {
    asm volatile("ldmatrix.sync.aligned.m8n8.x4.shared.b16 {%0,%1,%2,%3}, [%4];"
        : "=r"(r[0]), "=r"(r[1]), "=r"(r[2]), "=r"(r[3]) : "r"(addr));
}

// Warp computes 16m x 64n of A[*][K] * W[64][K]^T (bf16x3, ldmatrix).
// acc[nt][*]: nt-th 8-col tile. Strides sa/sw in u32 (must be ≡4 mod 32).
template <int KSTEPS>
__device__ __forceinline__ void warp_mma64(
    const u32* Ahi, const u32* Alo, int sa,
    const u32* Whi, const u32* Wlo, int sw,
    int m0, int lane, float acc[8][4])
{
    const int mat = lane >> 3, rin = lane & 7;
    u32 aOff = (u32)(((m0 + rin + ((mat & 1) << 3)) * sa + ((mat >> 1) << 2)) << 2);
    u32 aHiA = (u32)__cvta_generic_to_shared(Ahi) + aOff;
    u32 aLoA = (u32)__cvta_generic_to_shared(Alo) + aOff;
    u32 bRel = (u32)((((((mat >> 1) << 3)) + rin) * sw + ((mat & 1) << 2)) << 2);
    u32 wHiB = (u32)__cvta_generic_to_shared(Whi) + bRel;
    u32 wLoB = (u32)__cvta_generic_to_shared(Wlo) + bRel;

#pragma unroll
    for (int ks = 0; ks < KSTEPS; ks++) {
        const u32 kb = ks * 32;           // 8 u32 per k16 step
        u32 ah[4], al[4];
        ldsm4(ah, aHiA + kb);
        ldsm4(al, aLoA + kb);
#pragma unroll
        for (int nb = 0; nb < 4; nb++) {
            u32 bh[4], bl[4];
            u32 off = kb + (u32)(nb * 16 * sw * 4);
            ldsm4(bh, wHiB + off);
            ldsm4(bl, wLoB + off);
            mma16816(acc[2 * nb],     ah, bh + 0);
            mma16816(acc[2 * nb + 1], ah, bh + 2);
            mma16816(acc[2 * nb],     al, bh + 0);
            mma16816(acc[2 * nb + 1], al, bh + 2);
            mma16816(acc[2 * nb],     ah, bl + 0);
            mma16816(acc[2 * nb + 1], ah, bl + 2);
        }
    }
}

// =====================================================================
// Kernel 0: pre-split weights + zero counters
// =====================================================================
__global__ void split_kernel(const float* __restrict__ fW1,
                             const float* __restrict__ fW2,
                             const float* __restrict__ oW1)
{
    int i = blockIdx.x * blockDim.x + threadIdx.x;
    if (i < N_OPT) { g_counts[i] = 0; g_cursor[i] = 0; }
    if (i < 8192) {
        float2 v = ((const float2*)fW1)[i];
        split2(v.x, v.y, d_fW1h[i], d_fW1l[i]);
    } else if (i < 12288) {
        int k = i - 8192;
        float2 v = ((const float2*)fW2)[k];
        split2(v.x, v.y, d_fW2h[k], d_fW2l[k]);
    } else if (i < 45056) {
        int k = i - 12288;
        float2 v = ((const float2*)oW1)[k];
        split2(v.x, v.y, d_oW1h[k], d_oW1l[k]);
    }
}

// =====================================================================
// Kernel 1: trunk GEMMs (bf16x3 MMA), register-resident heads, histogram
// smem u32: aHi 4608 | aLo 4608 | wH 2304 | wL 2304 | hHi 4608 | hLo 4608
//           s_pt (2048 f32) aliases aHi (staged after phase 1)
// total 23040 u32 = 92160 B
// =====================================================================
__global__ void __launch_bounds__(256, 2) trunk_kernel(
    const float* __restrict__ obs, const int* __restrict__ opt,
    const float* __restrict__ fb1, const float* __restrict__ fb2,
    const float* __restrict__ pW,  const float* __restrict__ pb,
    const float* __restrict__ tW,  const float* __restrict__ tb,
    float* __restrict__ out_opt, float* __restrict__ out_term)
{
    extern __shared__ u32 smu[];
    u32* aHi = smu;              // 128*36
    u32* aLo = smu + 4608;
    u32* wH  = smu + 9216;       // 64*36
    u32* wL  = smu + 11520;
    u32* hHi = smu + 13824;      // 128*36
    u32* hLo = smu + 18432;
    float* s_pt = (float*)smu;   // alias aHi/aLo: pW [0..1023], tW [1024..2047]
    __shared__ int s_opt[TB];
    __shared__ int s_cnt[N_OPT];

    const int tid  = threadIdx.x;
    const int r0   = blockIdx.x * TB;
    const int w    = tid >> 5, lane = tid & 31;
    const int g    = lane >> 2, t = lane & 3;
    const int m0   = w * 16;
    if (tid < N_OPT) s_cnt[tid] = 0;
    if (tid < TB) s_opt[tid] = opt[r0 + tid];

    // ---------- phase 1: h = relu(obs @ fW1^T + fb1), K=256 in 4 chunks ----------
    float acc[8][4];
#pragma unroll
    for (int i = 0; i < 8; i++)
#pragma unroll
        for (int j = 0; j < 4; j++) acc[i][j] = 0.f;

    for (int kc = 0; kc < 4; kc++) {
        // obs chunk: 128 rows x 32 u32, split inline
#pragma unroll
        for (int it = 0; it < 16; it++) {
            int e = tid + it * 256;
            int row = e >> 5, p = e & 31;
            float2 ov = *(const float2*)(obs + (r0 + row) * OBS_DIM + kc * 64 + 2 * p);
            split2(ov.x, ov.y, aHi[row * 36 + p], aLo[row * 36 + p]);
        }
        // fW1 chunk: 512 uint4 copies
#pragma unroll
        for (int it = 0; it < 2; it++) {
            int q = tid + it * 256;
            int row = q >> 3, p4 = (q & 7) << 2;
            *(uint4*)(wH + row * 36 + p4) = *(const uint4*)(d_fW1h + row * 128 + kc * 32 + p4);
            *(uint4*)(wL + row * 36 + p4) = *(const uint4*)(d_fW1l + row * 128 + kc * 32 + p4);
        }
        __syncthreads();
        warp_mma64<4>(aHi, aLo, 36, wH, wL, 36, m0, lane, acc);
        __syncthreads();
    }
    // phase-1 epilogue -> h (bf16 hi/lo) rows m0+g, m0+g+8
    {
        const int r1 = m0 + g, r2 = m0 + g + 8;
#pragma unroll
        for (int nt = 0; nt < 8; nt++) {
            int c = nt * 8 + 2 * t;
            float b0 = fb1[c], b1 = fb1[c + 1];
            float v0 = fmaxf(acc[nt][0] + b0, 0.f), v1 = fmaxf(acc[nt][1] + b1, 0.f);
            split2(v0, v1, hHi[r1 * 36 + (c >> 1)], hLo[r1 * 36 + (c >> 1)]);
            float v2 = fmaxf(acc[nt][2] + b0, 0.f), v3 = fmaxf(acc[nt][3] + b1, 0.f);
            split2(v2, v3, hHi[r2 * 36 + (c >> 1)], hLo[r2 * 36 + (c >> 1)]);
        }
    }

    // ---------- phase 2: state = relu(h @ fW2^T + fb2), N=128 in 2 halves ----------
    const int r1 = m0 + g, r2 = m0 + g + 8;
    const int o1 = s_opt[r1], o2 = s_opt[r2];
    float pv1 = 0.f, tv1 = 0.f, pv2 = 0.f, tv2 = 0.f;

#pragma unroll
    for (int nh = 0; nh < 2; nh++) {
#pragma unroll
        for (int it = 0; it < 2; it++) {
            int q = tid + it * 256;
            int row = q >> 3, p4 = (q & 7) << 2;
            *(uint4*)(wH + row * 36 + p4) = *(const uint4*)(d_fW2h + (nh * 64 + row) * 32 + p4);
            *(uint4*)(wL + row * 36 + p4) = *(const uint4*)(d_fW2l + (nh * 64 + row) * 32 + p4);
        }
        if (nh == 0) {
            // stage pW/tW into aliased region (aHi/aLo dead after phase 1)
#pragma unroll
            for (int it = 0; it < 8; it++) {
                int e = tid + it * 256;
                s_pt[e] = (e < 1024) ? pW[e] : tW[e - 1024];
            }
        }
        __syncthreads();

        float acc2[8][4];
#pragma unroll
        for (int i = 0; i < 8; i++)
#pragma unroll
            for (int j = 0; j < 4; j++) acc2[i][j] = 0.f;
        warp_mma64<4>(hHi, hLo, 36, wH, wL, 36, m0, lane, acc2);

        // epilogue: state -> global bf16 hi/lo; head partials in registers
#pragma unroll
        for (int nt = 0; nt < 8; nt++) {
            int c = nh * 64 + nt * 8 + 2 * t;
            float b0 = fb2[c], b1 = fb2[c + 1];
            float v0 = fmaxf(acc2[nt][0] + b0, 0.f);
            float v1 = fmaxf(acc2[nt][1] + b1, 0.f);
            float v2 = fmaxf(acc2[nt][2] + b0, 0.f);
            float v3 = fmaxf(acc2[nt][3] + b1, 0.f);
            u32 hi, lo;
            split2(v0, v1, hi, lo);
            g_stateh[(r0 + r1) * 64 + (c >> 1)] = hi;
            g_statel[(r0 + r1) * 64 + (c >> 1)] = lo;
            split2(v2, v3, hi, lo);
            g_stateh[(r0 + r2) * 64 + (c >> 1)] = hi;
            g_statel[(r0 + r2) * 64 + (c >> 1)] = lo;
            pv1 += v0 * s_pt[o1 * 128 + c] + v1 * s_pt[o1 * 128 + c + 1];
            tv1 += v0 * s_pt[1024 + o1 * 128 + c] + v1 * s_pt[1024 + o1 * 128 + c + 1];
            pv2 += v2 * s_pt[o2 * 128 + c] + v3 * s_pt[o2 * 128 + c + 1];
            tv2 += v2 * s_pt[1024 + o2 * 128 + c] + v3 * s_pt[1024 + o2 * 128 + c + 1];
        }
        __syncthreads();
    }

    // quad-reduce heads (lanes t=0..3 share rows r1/r2)
#pragma unroll
    for (int o = 1; o <= 2; o <<= 1) {
        pv1 += __shfl_xor_sync(0xffffffffu, pv1, o);
        tv1 += __shfl_xor_sync(0xffffffffu, tv1, o);
        pv2 += __shfl_xor_sync(0xffffffffu, pv2, o);
        tv2 += __shfl_xor_sync(0xffffffffu, tv2, o);
    }
    if (t == 0) {
        out_opt[r0 + r1]  = pv1 + pb[o1];
        out_term[r0 + r1] = 1.f / (1.f + expf(-(tv1 + tb[o1])));
        out_opt[r0 + r2]  = pv2 + pb[o2];
        out_term[r0 + r2] = 1.f / (1.f + expf(-(tv2 + tb[o2])));
    }

    // histogram
    if (tid < TB) atomicAdd(&s_cnt[s_opt[tid]], 1);
    __syncthreads();
    if (tid < N_OPT && s_cnt[tid]) atomicAdd(&g_counts[tid], s_cnt[tid]);
}

// =====================================================================
// Kernel 2: scatter (local 8-bin prefix of g_counts; no separate scan)
// =====================================================================
__global__ void scatter_kernel(const int* __restrict__ opt)
{
    __shared__ int s_c[N_OPT];
    __shared__ int s_base[N_OPT];
    int t = threadIdx.x;
    if (t < N_OPT) s_c[t] = 0;
    __syncthreads();
    int i = blockIdx.x * blockDim.x + t;
    int o = opt[i];
    int loc = atomicAdd(&s_c[o], 1);
    __syncthreads();
    if (t < N_OPT) {
        int base = 0;
        for (int q = 0; q < t; q++) base += g_counts[q];
        s_base[t] = base + atomicAdd(&g_cursor[t], s_c[t]);
    }
    __syncthreads();
    g_perm[s_base[o] + loc] = i;
}

// =====================================================================
// Kernel 3: expert MLP (bf16x3 MMA, TB=128) + fused logits/log-softmax
// smem u32: stHi 8704 | stLo 8704 | wHi 4352 | wLo 4352 | s_w2 1188
// s_eh (128*66 f32 = 8448) aliases wHi+wLo after MMA
// total 27300 u32 = 109200 B
// =====================================================================
__global__ void __launch_bounds__(256, 2) expert_kernel(
    const float* __restrict__ ob1,
    const float* __restrict__ oW2, const float* __restrict__ ob2,
    const int* __restrict__ opt, const int* __restrict__ act,
    float* __restrict__ out_logp)
{
    extern __shared__ u32 smu[];
    u32* stHi = smu;                       // 128*68
    u32* stLo = smu + 8704;
    u32* wHi  = smu + 17408;               // 64*68
    u32* wLo  = smu + 21760;
    float* s_eh = (float*)(smu + 17408);   // alias wHi+wLo (after MMA)
    float* s_w2 = (float*)(smu + 26112);   // 18*66
    __shared__ int s_idx[TB];
    __shared__ int s_opt[TB];

    const int tid  = threadIdx.x;
    const int r0   = blockIdx.x * TB;
    const int w    = tid >> 5, lane = tid & 31;
    const int g    = lane >> 2, t = lane & 3;
    const int m0   = w * 16;

    if (tid < TB) {
        int gi = g_perm[r0 + tid];
        s_idx[tid] = gi;
        s_opt[tid] = opt[gi];
    }
    __syncthreads();
    // gather pre-split state rows (uint4)
#pragma unroll
    for (int it = 0; it < 8; it++) {
        int q = tid + it * 256;                 // 2048 uint4
        int row = q >> 4, p4 = (q & 15) << 2;
        int gi = s_idx[row];
        *(uint4*)(stHi + row * 68 + p4) = *(const uint4*)(g_stateh + gi * 64 + p4);
        *(uint4*)(stLo + row * 68 + p4) = *(const uint4*)(g_statel + gi * 64 + p4);
    }
    __syncthreads();

    int j = 0;
    while (j < TB) {
        const int o = s_opt[j];
        int re = j + 1;
        while (re < TB && s_opt[re] == o) re++;

        // stage pre-split oW1[o]
#pragma unroll
        for (int it = 0; it < 4; it++) {
            int q = tid + it * 256;
            int row = q >> 4, p4 = (q & 15) << 2;
            *(uint4*)(wHi + row * 68 + p4) = *(const uint4*)(d_oW1h + (o * 64 + row) * 64 + p4);
            *(uint4*)(wLo + row * 68 + p4) = *(const uint4*)(d_oW1l + (o * 64 + row) * 64 + p4);
        }
        __syncthreads();

        // eh = relu(state @ W1^T + b1), K=128
        float acc[8][4];
#pragma unroll
        for (int i = 0; i < 8; i++)
#pragma unroll
            for (int q = 0; q < 4; q++) acc[i][q] = 0.f;
        warp_mma64<8>(stHi, stLo, 68, wHi, wLo, 68, m0, lane, acc);
        __syncthreads();   // done reading wHi/wLo before aliasing as s_eh

        // guarded epilogue -> s_eh (rows in [j, re))
        {
            const int r1 = m0 + g, r2 = m0 + g + 8;
#pragma unroll
            for (int nt = 0; nt < 8; nt++) {
                int c = nt * 8 + 2 * t;
                float b0 = ob1[o * HID + c], b1 = ob1[o * HID + c + 1];
                if (r1 >= j && r1 < re) {
                    s_eh[r1 * 66 + c]     = fmaxf(acc[nt][0] + b0, 0.f);
                    s_eh[r1 * 66 + c + 1] = fmaxf(acc[nt][1] + b1, 0.f);
                }
                if (r2 >= j && r2 < re) {
                    s_eh[r2 * 66 + c]     = fmaxf(acc[nt][2] + b0, 0.f);
                    s_eh[r2 * 66 + c + 1] = fmaxf(acc[nt][3] + b1, 0.f);
                }
            }
        }
        // stage oW2[o] -> s_w2
#pragma unroll
        for (int it = 0; it < 3; it++) {
            int e = tid + it * 256;                 // 576 float2 slots
            if (e < ACT_N * 32) {
                int a = e >> 5, h2 = (e & 31) << 1;
                *(float2*)(s_w2 + a * 66 + h2) =
                    *(const float2*)(oW2 + o * ACT_N * HID + a * HID + h2);
            }
        }
        __syncthreads();

        // fused logits + log-softmax: warp per row, lane = action
        for (int r = j + w; r < re; r += 8) {
            float v = -INFINITY;
            if (lane < ACT_N) {
                ull s0 = 0ull, s1 = 0ull;
#pragma unroll
                for (int h = 0; h < HID; h += 4) {
                    s0 = ffma2(lds2(s_eh + r * 66 + h),     lds2(s_w2 + lane * 66 + h),     s0);
                    s1 = ffma2(lds2(s_eh + r * 66 + h + 2), lds2(s_w2 + lane * 66 + h + 2), s1);
                }
                v = f2sum(s0) + f2sum(s1) + ob2[o * ACT_N + lane];
            }
            float m = wred_max(v);
            float ex = (lane < ACT_N) ? expf(v - m) : 0.f;
            float S = wred_sum(ex);
            int gi = s_idx[r];
            int a  = act[gi];
            float va = __shfl_sync(0xffffffffu, v, a);
            if (lane == 0) out_logp[gi] = va - m - logf(S);
        }
        __syncthreads();
        j = re;
    }
}

// =====================================================================
extern "C" void kernel_launch(void* const* d_in, const int* in_sizes, int n_in,
                              void* d_out, int out_size)
{
    const float* obs = (const float*)d_in[0];
    const int*   act = (const int*)  d_in[1];
    const int*   opt = (const int*)  d_in[2];
    const float* fW1 = (const float*)d_in[3];
    const float* fb1 = (const float*)d_in[4];
    const float* fW2 = (const float*)d_in[5];
    const float* fb2 = (const float*)d_in[6];
    const float* pW  = (const float*)d_in[7];
    const float* pb  = (const float*)d_in[8];
    const float* tW  = (const float*)d_in[9];
    const float* tb  = (const float*)d_in[10];
    const float* oW1 = (const float*)d_in[11];
    const float* ob1 = (const float*)d_in[12];
    const float* oW2 = (const float*)d_in[13];
    const float* ob2 = (const float*)d_in[14];

    float* out_logp = (float*)d_out;
    float* out_opt  = out_logp + B_TOT;
    float* out_term = out_logp + 2 * B_TOT;

    const int smem1 = 23040 * 4;   // 92,160 B
    const int smem4 = 27300 * 4;   // 109,200 B
    cudaFuncSetAttribute(trunk_kernel,  cudaFuncAttributeMaxDynamicSharedMemorySize, smem1);
    cudaFuncSetAttribute(expert_kernel, cudaFuncAttributeMaxDynamicSharedMemorySize, smem4);

    split_kernel<<<176, 256>>>(fW1, fW2, oW1);
    trunk_kernel<<<B_TOT / TB, 256, smem1>>>(obs, opt, fb1, fb2,
                                             pW, pb, tW, tb, out_opt, out_term);
    scatter_kernel<<<B_TOT / 256, 256>>>(opt);
    expert_kernel<<<B_TOT / TB, 256, smem4>>>(ob1, oW2, ob2, opt, act, out_logp);
}

// round 7
// speedup vs baseline: 2.1721x; 1.3183x over previous
#include <cuda_runtime.h>
#include <cuda_bf16.h>
#include <math.h>

#define B_TOT   32768
#define OBS_DIM 256
#define HID     64
#define FEAT    128
#define N_OPT   8
#define ACT_N   18
#define TB      128

typedef unsigned long long ull;
typedef unsigned u32;

// ---------------- scratch (no allocation allowed) ----------------
__device__ u32  g_stateh[B_TOT * 64];
__device__ u32  g_statel[B_TOT * 64];
__device__ int  g_perm[B_TOT];
__device__ int  g_counts[N_OPT];
__device__ int  g_cursor[N_OPT];
// pre-split weights (packed bf16x2 along K)
__device__ u32  d_fW1h[64 * 128],  d_fW1l[64 * 128];
__device__ u32  d_fW2h[128 * 32],  d_fW2l[128 * 32];
__device__ u32  d_oW1h[8 * 64 * 64], d_oW1l[8 * 64 * 64];
__device__ u32  d_oW2h[8 * 24 * 32], d_oW2l[8 * 24 * 32];   // zero-padded 24-row image

// ---------------- helpers ----------------
__device__ __forceinline__ void cp16(u32 dst, const void* src) {
    asm volatile("cp.async.cg.shared.global [%0], [%1], 16;" :: "r"(dst), "l"(src));
}
__device__ __forceinline__ void cp_commit_wait0() {
    asm volatile("cp.async.commit_group;");
    asm volatile("cp.async.wait_group 0;" ::: "memory");
}
__device__ __forceinline__ void split2(float x, float y, u32& hi, u32& lo) {
    __nv_bfloat162 h = __floats2bfloat162_rn(x, y);
    float hx = __bfloat162float(h.x);
    float hy = __bfloat162float(h.y);
    __nv_bfloat162 l = __floats2bfloat162_rn(x - hx, y - hy);
    hi = *reinterpret_cast<u32*>(&h);
    lo = *reinterpret_cast<u32*>(&l);
}
__device__ __forceinline__ void mma16816(float d[4], const u32 a[4], const u32 b[2]) {
    asm("mma.sync.aligned.m16n8k16.row.col.f32.bf16.bf16.f32 "
        "{%0,%1,%2,%3},{%4,%5,%6,%7},{%8,%9},{%0,%1,%2,%3};"
        : "+f"(d[0]), "+f"(d[1]), "+f"(d[2]), "+f"(d[3])
        : "r"(a[0]), "r"(a[1]), "r"(a[2]), "r"(a[3]), "r"(b[0]), "r"(b[1]));
}
__device__ __forceinline__ void ldsm4(u32 r[4], u32 addr) {
    asm volatile("ldmatrix.sync.aligned.m8n8.x4.shared.b16 {%0,%1,%2,%3}, [%4];"
        : "=r"(r[0]), "=r"(r[1]), "=r"(r[2]), "=r"(r[3]) : "r"(addr));
}
__device__ __forceinline__ void ldsm2(u32 r[2], u32 addr) {
    asm volatile("ldmatrix.sync.aligned.m8n8.x2.shared.b16 {%0,%1}, [%2];"
        : "=r"(r[0]), "=r"(r[1]) : "r"(addr));
}

// Warp computes 16m x 64n of A[*][K] * W[64][K]^T (bf16x3, ldmatrix).
template <int KSTEPS>
__device__ __forceinline__ void warp_mma64(
    const u32* Ahi, const u32* Alo, int sa,
    const u32* Whi, const u32* Wlo, int sw,
    int m0, int lane, float acc[8][4])
{
    const int mat = lane >> 3, rin = lane & 7;
    u32 aOff = (u32)(((m0 + rin + ((mat & 1) << 3)) * sa + ((mat >> 1) << 2)) << 2);
    u32 aHiA = (u32)__cvta_generic_to_shared(Ahi) + aOff;
    u32 aLoA = (u32)__cvta_generic_to_shared(Alo) + aOff;
    u32 bRel = (u32)((((((mat >> 1) << 3)) + rin) * sw + ((mat & 1) << 2)) << 2);
    u32 wHiB = (u32)__cvta_generic_to_shared(Whi) + bRel;
    u32 wLoB = (u32)__cvta_generic_to_shared(Wlo) + bRel;

#pragma unroll
    for (int ks = 0; ks < KSTEPS; ks++) {
        const u32 kb = ks * 32;
        u32 ah[4], al[4];
        ldsm4(ah, aHiA + kb);
        ldsm4(al, aLoA + kb);
#pragma unroll
        for (int nb = 0; nb < 4; nb++) {
            u32 bh[4], bl[4];
            u32 off = kb + (u32)(nb * 16 * sw * 4);
            ldsm4(bh, wHiB + off);
            ldsm4(bl, wLoB + off);
            mma16816(acc[2 * nb],     ah, bh + 0);
            mma16816(acc[2 * nb + 1], ah, bh + 2);
            mma16816(acc[2 * nb],     al, bh + 0);
            mma16816(acc[2 * nb + 1], al, bh + 2);
            mma16816(acc[2 * nb],     ah, bl + 0);
            mma16816(acc[2 * nb + 1], ah, bl + 2);
        }
    }
}

// =====================================================================
// Kernel 0: pre-split weights + oW2 image + opt histogram
// =====================================================================
__global__ void split_kernel(const float* __restrict__ fW1,
                             const float* __restrict__ fW2,
                             const float* __restrict__ oW1,
                             const float* __restrict__ oW2,
                             const int* __restrict__ opt)
{
    __shared__ int s_cnt[N_OPT];
    int tid = threadIdx.x;
    if (tid < N_OPT) s_cnt[tid] = 0;
    __syncthreads();
    int i = blockIdx.x * blockDim.x + tid;
    if (i < 8192) {
        float2 v = ((const float2*)fW1)[i];
        split2(v.x, v.y, d_fW1h[i], d_fW1l[i]);
    } else if (i < 12288) {
        int k = i - 8192;
        float2 v = ((const float2*)fW2)[k];
        split2(v.x, v.y, d_fW2h[k], d_fW2l[k]);
    } else if (i < 45056) {
        int k = i - 12288;
        float2 v = ((const float2*)oW1)[k];
        split2(v.x, v.y, d_oW1h[k], d_oW1l[k]);
    } else if (i < 45056 + 8 * 24 * 32) {
        int k = i - 45056;                    // [opt][24][32]
        int o = k / 768, row = (k % 768) / 32, p = k % 32;
        u32 hi = 0, lo = 0;
        if (row < ACT_N) {
            float2 v = *(const float2*)(oW2 + (o * ACT_N + row) * HID + 2 * p);
            split2(v.x, v.y, hi, lo);
        }
        d_oW2h[k] = hi;
        d_oW2l[k] = lo;
    }
    if (i < B_TOT) atomicAdd(&s_cnt[opt[i]], 1);
    __syncthreads();
    if (tid < N_OPT && s_cnt[tid]) atomicAdd(&g_counts[tid], s_cnt[tid]);
}

// =====================================================================
// Kernel 1: trunk GEMMs (bf16x3 MMA), register-resident heads
// =====================================================================
__global__ void __launch_bounds__(256, 2) trunk_kernel(
    const float* __restrict__ obs, const int* __restrict__ opt,
    const float* __restrict__ fb1, const float* __restrict__ fb2,
    const float* __restrict__ pW,  const float* __restrict__ pb,
    const float* __restrict__ tW,  const float* __restrict__ tb,
    float* __restrict__ out_opt, float* __restrict__ out_term)
{
    extern __shared__ u32 smu[];
    u32* aHi = smu;              // 128*36
    u32* aLo = smu + 4608;
    u32* wH  = smu + 9216;       // 64*36
    u32* wL  = smu + 11520;
    u32* hHi = smu + 13824;      // 128*36
    u32* hLo = smu + 18432;
    float* s_pt = (float*)smu;   // alias aHi/aLo after phase 1
    __shared__ int s_opt[TB];

    const int tid  = threadIdx.x;
    const int r0   = blockIdx.x * TB;
    const int w    = tid >> 5, lane = tid & 31;
    const int g    = lane >> 2, t = lane & 3;
    const int m0   = w * 16;
    if (tid < TB) s_opt[tid] = opt[r0 + tid];

    // ---------- phase 1 ----------
    float acc[8][4];
#pragma unroll
    for (int i = 0; i < 8; i++)
#pragma unroll
        for (int j = 0; j < 4; j++) acc[i][j] = 0.f;

    for (int kc = 0; kc < 4; kc++) {
        // fW1 chunk via cp.async (issue first, overlap with obs split)
#pragma unroll
        for (int it = 0; it < 2; it++) {
            int q = tid + it * 256;
            int row = q >> 3, p4 = (q & 7) << 2;
            cp16((u32)__cvta_generic_to_shared(wH + row * 36 + p4),
                 d_fW1h + row * 128 + kc * 32 + p4);
            cp16((u32)__cvta_generic_to_shared(wL + row * 36 + p4),
                 d_fW1l + row * 128 + kc * 32 + p4);
        }
        // obs chunk split inline
#pragma unroll
        for (int it = 0; it < 16; it++) {
            int e = tid + it * 256;
            int row = e >> 5, p = e & 31;
            float2 ov = *(const float2*)(obs + (r0 + row) * OBS_DIM + kc * 64 + 2 * p);
            split2(ov.x, ov.y, aHi[row * 36 + p], aLo[row * 36 + p]);
        }
        cp_commit_wait0();
        __syncthreads();
        warp_mma64<4>(aHi, aLo, 36, wH, wL, 36, m0, lane, acc);
        __syncthreads();
    }
    // epilogue -> h bf16 hi/lo
    {
        const int r1 = m0 + g, r2 = m0 + g + 8;
#pragma unroll
        for (int nt = 0; nt < 8; nt++) {
            int c = nt * 8 + 2 * t;
            float b0 = fb1[c], b1 = fb1[c + 1];
            float v0 = fmaxf(acc[nt][0] + b0, 0.f), v1 = fmaxf(acc[nt][1] + b1, 0.f);
            split2(v0, v1, hHi[r1 * 36 + (c >> 1)], hLo[r1 * 36 + (c >> 1)]);
            float v2 = fmaxf(acc[nt][2] + b0, 0.f), v3 = fmaxf(acc[nt][3] + b1, 0.f);
            split2(v2, v3, hHi[r2 * 36 + (c >> 1)], hLo[r2 * 36 + (c >> 1)]);
        }
    }

    // ---------- phase 2 ----------
    const int r1 = m0 + g, r2 = m0 + g + 8;
    const int o1 = s_opt[r1], o2 = s_opt[r2];
    float pv1 = 0.f, tv1 = 0.f, pv2 = 0.f, tv2 = 0.f;

#pragma unroll
    for (int nh = 0; nh < 2; nh++) {
#pragma unroll
        for (int it = 0; it < 2; it++) {
            int q = tid + it * 256;
            int row = q >> 3, p4 = (q & 7) << 2;
            cp16((u32)__cvta_generic_to_shared(wH + row * 36 + p4),
                 d_fW2h + (nh * 64 + row) * 32 + p4);
            cp16((u32)__cvta_generic_to_shared(wL + row * 36 + p4),
                 d_fW2l + (nh * 64 + row) * 32 + p4);
        }
        if (nh == 0) {
            // s_pt: 2048 f32 = 512 uint4
#pragma unroll
            for (int it = 0; it < 2; it++) {
                int q = tid + it * 256;
                const float* src = (q < 256) ? (pW + q * 4) : (tW + (q - 256) * 4);
                cp16((u32)__cvta_generic_to_shared(s_pt + q * 4), src);
            }
        }
        cp_commit_wait0();
        __syncthreads();

        float acc2[8][4];
#pragma unroll
        for (int i = 0; i < 8; i++)
#pragma unroll
            for (int j = 0; j < 4; j++) acc2[i][j] = 0.f;
        warp_mma64<4>(hHi, hLo, 36, wH, wL, 36, m0, lane, acc2);

#pragma unroll
        for (int nt = 0; nt < 8; nt++) {
            int c = nh * 64 + nt * 8 + 2 * t;
            float b0 = fb2[c], b1 = fb2[c + 1];
            float v0 = fmaxf(acc2[nt][0] + b0, 0.f);
            float v1 = fmaxf(acc2[nt][1] + b1, 0.f);
            float v2 = fmaxf(acc2[nt][2] + b0, 0.f);
            float v3 = fmaxf(acc2[nt][3] + b1, 0.f);
            u32 hi, lo;
            split2(v0, v1, hi, lo);
            g_stateh[(r0 + r1) * 64 + (c >> 1)] = hi;
            g_statel[(r0 + r1) * 64 + (c >> 1)] = lo;
            split2(v2, v3, hi, lo);
            g_stateh[(r0 + r2) * 64 + (c >> 1)] = hi;
            g_statel[(r0 + r2) * 64 + (c >> 1)] = lo;
            pv1 += v0 * s_pt[o1 * 128 + c] + v1 * s_pt[o1 * 128 + c + 1];
            tv1 += v0 * s_pt[1024 + o1 * 128 + c] + v1 * s_pt[1024 + o1 * 128 + c + 1];
            pv2 += v2 * s_pt[o2 * 128 + c] + v3 * s_pt[o2 * 128 + c + 1];
            tv2 += v2 * s_pt[1024 + o2 * 128 + c] + v3 * s_pt[1024 + o2 * 128 + c + 1];
        }
        __syncthreads();
    }

#pragma unroll
    for (int o = 1; o <= 2; o <<= 1) {
        pv1 += __shfl_xor_sync(0xffffffffu, pv1, o);
        tv1 += __shfl_xor_sync(0xffffffffu, tv1, o);
        pv2 += __shfl_xor_sync(0xffffffffu, pv2, o);
        tv2 += __shfl_xor_sync(0xffffffffu, tv2, o);
    }
    if (t == 0) {
        out_opt[r0 + r1]  = pv1 + pb[o1];
        out_term[r0 + r1] = 1.f / (1.f + expf(-(tv1 + tb[o1])));
        out_opt[r0 + r2]  = pv2 + pb[o2];
        out_term[r0 + r2] = 1.f / (1.f + expf(-(tv2 + tb[o2])));
    }
}

// =====================================================================
// Kernel 2: scatter (local prefix of g_counts, atomic cursors)
// =====================================================================
__global__ void scatter_kernel(const int* __restrict__ opt)
{
    __shared__ int s_c[N_OPT];
    __shared__ int s_base[N_OPT];
    int t = threadIdx.x;
    if (t < N_OPT) s_c[t] = 0;
    __syncthreads();
    int i = blockIdx.x * blockDim.x + t;
    int o = opt[i];
    int loc = atomicAdd(&s_c[o], 1);
    __syncthreads();
    if (t < N_OPT) {
        int base = 0;
        for (int q = 0; q < t; q++) base += g_counts[q];
        s_base[t] = base + atomicAdd(&g_cursor[t], s_c[t]);
    }
    __syncthreads();
    g_perm[s_base[o] + loc] = i;
}

// =====================================================================
// Kernel 3: expert — MMA1 + register-fragment MMA2 logits + softmax
// smem u32: stHi 8704 | stLo 8704 | wHi 4352 | wLo 4352 | w2h 864 | w2l 864
// =====================================================================
__global__ void __launch_bounds__(256, 2) expert_kernel(
    const float* __restrict__ ob1, const float* __restrict__ ob2,
    const int* __restrict__ opt, const int* __restrict__ act,
    float* __restrict__ out_logp)
{
    extern __shared__ u32 smu[];
    u32* stHi = smu;
    u32* stLo = smu + 8704;
    u32* wHi  = smu + 17408;
    u32* wLo  = smu + 21760;
    u32* w2h  = smu + 26112;
    u32* w2l  = smu + 26976;
    __shared__ int s_idx[TB];
    __shared__ int s_opt[TB];
    __shared__ int s_act[TB];

    const int tid  = threadIdx.x;
    const int r0   = blockIdx.x * TB;
    const int w    = tid >> 5, lane = tid & 31;
    const int g    = lane >> 2, t = lane & 3;
    const int m0   = w * 16;

    // reset sort counters for next graph replay (consumed already this run)
    if (blockIdx.x == 0 && tid < N_OPT) { g_counts[tid] = 0; g_cursor[tid] = 0; }

    if (tid < TB) {
        int gi = g_perm[r0 + tid];
        s_idx[tid] = gi;
        s_opt[tid] = opt[gi];
        s_act[tid] = act[gi];
    }
    __syncthreads();

    // state gather via cp.async
#pragma unroll
    for (int it = 0; it < 8; it++) {
        int q = tid + it * 256;
        int row = q >> 4, p4 = (q & 15) << 2;
        int gi = s_idx[row];
        cp16((u32)__cvta_generic_to_shared(stHi + row * 68 + p4), g_stateh + gi * 64 + p4);
        cp16((u32)__cvta_generic_to_shared(stLo + row * 68 + p4), g_statel + gi * 64 + p4);
    }
    // first-run weights
    {
        int o = s_opt[0];
#pragma unroll
        for (int it = 0; it < 4; it++) {
            int q = tid + it * 256;
            int row = q >> 4, p4 = (q & 15) << 2;
            cp16((u32)__cvta_generic_to_shared(wHi + row * 68 + p4), d_oW1h + (o * 64 + row) * 64 + p4);
            cp16((u32)__cvta_generic_to_shared(wLo + row * 68 + p4), d_oW1l + (o * 64 + row) * 64 + p4);
        }
        if (tid < 192) {
            int row = tid >> 3, p4 = (tid & 7) << 2;
            cp16((u32)__cvta_generic_to_shared(w2h + row * 36 + p4), d_oW2h + o * 768 + row * 32 + p4);
            cp16((u32)__cvta_generic_to_shared(w2l + row * 36 + p4), d_oW2l + o * 768 + row * 32 + p4);
        }
    }
    cp_commit_wait0();
    __syncthreads();

    int j = 0;
    bool first = true;
    while (j < TB) {
        const int o = s_opt[j];
        int re = j + 1;
        while (re < TB && s_opt[re] == o) re++;

        if (!first) {
            __syncthreads();   // prior run's MMA reads done
#pragma unroll
            for (int it = 0; it < 4; it++) {
                int q = tid + it * 256;
                int row = q >> 4, p4 = (q & 15) << 2;
                cp16((u32)__cvta_generic_to_shared(wHi + row * 68 + p4), d_oW1h + (o * 64 + row) * 64 + p4);
                cp16((u32)__cvta_generic_to_shared(wLo + row * 68 + p4), d_oW1l + (o * 64 + row) * 64 + p4);
            }
            if (tid < 192) {
                int row = tid >> 3, p4 = (tid & 7) << 2;
                cp16((u32)__cvta_generic_to_shared(w2h + row * 36 + p4), d_oW2h + o * 768 + row * 32 + p4);
                cp16((u32)__cvta_generic_to_shared(w2l + row * 36 + p4), d_oW2l + o * 768 + row * 32 + p4);
            }
            cp_commit_wait0();
            __syncthreads();
        }
        first = false;

        // ---- MMA1: eh-pre = state @ W1^T ----
        float acc[8][4];
#pragma unroll
        for (int i = 0; i < 8; i++)
#pragma unroll
            for (int q = 0; q < 4; q++) acc[i][q] = 0.f;
        warp_mma64<8>(stHi, stLo, 68, wHi, wLo, 68, m0, lane, acc);

        // ---- epilogue in registers: relu+bias -> bf16 hi/lo A-fragments ----
        u32 ah1[8], al1[8], ah2[8], al2[8];
#pragma unroll
        for (int nt = 0; nt < 8; nt++) {
            int c = nt * 8 + 2 * t;
            float b0 = ob1[o * HID + c], b1 = ob1[o * HID + c + 1];
            split2(fmaxf(acc[nt][0] + b0, 0.f), fmaxf(acc[nt][1] + b1, 0.f), ah1[nt], al1[nt]);
            split2(fmaxf(acc[nt][2] + b0, 0.f), fmaxf(acc[nt][3] + b1, 0.f), ah2[nt], al2[nt]);
        }

        // ---- MMA2: logits = eh @ W2^T (A from registers, B = w2 image) ----
        float accL[3][4];
#pragma unroll
        for (int i = 0; i < 3; i++)
#pragma unroll
            for (int q = 0; q < 4; q++) accL[i][q] = 0.f;
        {
            const int mat = lane >> 3, rin = lane & 7;
            u32 b4h = (u32)__cvta_generic_to_shared(w2h) +
                      (u32)(((((mat >> 1) << 3) + rin) * 36 + ((mat & 1) << 2)) << 2);
            u32 b4l = (u32)__cvta_generic_to_shared(w2l) +
                      (u32)(((((mat >> 1) << 3) + rin) * 36 + ((mat & 1) << 2)) << 2);
            const int l16 = lane & 15;
            u32 b2off = (u32)(((16 + (l16 & 7)) * 36 + (((l16 >> 3) & 1) << 2)) << 2);
            u32 b2h = (u32)__cvta_generic_to_shared(w2h) + b2off;
            u32 b2l = (u32)__cvta_generic_to_shared(w2l) + b2off;
#pragma unroll
            for (int ks = 0; ks < 4; ks++) {
                u32 kb = ks * 32;
                u32 ah[4] = { ah1[2 * ks], ah2[2 * ks], ah1[2 * ks + 1], ah2[2 * ks + 1] };
                u32 al[4] = { al1[2 * ks], al2[2 * ks], al1[2 * ks + 1], al2[2 * ks + 1] };
                u32 bh[4], bl[4], bh2[2], bl2[2];
                ldsm4(bh, b4h + kb);
                ldsm4(bl, b4l + kb);
                ldsm2(bh2, b2h + kb);
                ldsm2(bl2, b2l + kb);
                mma16816(accL[0], ah, bh + 0);
                mma16816(accL[1], ah, bh + 2);
                mma16816(accL[2], ah, bh2);
                mma16816(accL[0], al, bh + 0);
                mma16816(accL[1], al, bh + 2);
                mma16816(accL[2], al, bh2);
                mma16816(accL[0], ah, bl + 0);
                mma16816(accL[1], ah, bl + 2);
                mma16816(accL[2], ah, bl2);
            }
        }

        // ---- softmax on C-fragments (quad-wide) ----
#pragma unroll
        for (int half = 0; half < 2; half++) {
            int rr = m0 + g + half * 8;
            float v[3][2];
#pragma unroll
            for (int nt = 0; nt < 3; nt++)
#pragma unroll
                for (int i = 0; i < 2; i++) {
                    int c = nt * 8 + 2 * t + i;
                    v[nt][i] = (c < ACT_N) ? accL[nt][half * 2 + i] + ob2[o * ACT_N + c]
                                           : -INFINITY;
                }
            float m = v[0][0];
#pragma unroll
            for (int nt = 0; nt < 3; nt++)
#pragma unroll
                for (int i = 0; i < 2; i++) m = fmaxf(m, v[nt][i]);
            m = fmaxf(m, __shfl_xor_sync(0xffffffffu, m, 1));
            m = fmaxf(m, __shfl_xor_sync(0xffffffffu, m, 2));
            float S = 0.f;
#pragma unroll
            for (int nt = 0; nt < 3; nt++)
#pragma unroll
                for (int i = 0; i < 2; i++) S += expf(v[nt][i] - m);
            S += __shfl_xor_sync(0xffffffffu, S, 1);
            S += __shfl_xor_sync(0xffffffffu, S, 2);
            int a = s_act[rr];
            float cand = 0.f;
#pragma unroll
            for (int nt = 0; nt < 3; nt++)
#pragma unroll
                for (int i = 0; i < 2; i++) {
                    int c = nt * 8 + 2 * t + i;
                    cand = (c == a) ? v[nt][i] : cand;
                }
            cand += __shfl_xor_sync(0xffffffffu, cand, 1);
            cand += __shfl_xor_sync(0xffffffffu, cand, 2);
            if (t == 0 && rr >= j && rr < re)
                out_logp[s_idx[rr]] = cand - m - logf(S);
        }
        j = re;
    }
}

// =====================================================================
extern "C" void kernel_launch(void* const* d_in, const int* in_sizes, int n_in,
                              void* d_out, int out_size)
{
    const float* obs = (const float*)d_in[0];
    const int*   act = (const int*)  d_in[1];
    const int*   opt = (const int*)  d_in[2];
    const float* fW1 = (const float*)d_in[3];
    const float* fb1 = (const float*)d_in[4];
    const float* fW2 = (const float*)d_in[5];
    const float* fb2 = (const float*)d_in[6];
    const float* pW  = (const float*)d_in[7];
    const float* pb  = (const float*)d_in[8];
    const float* tW  = (const float*)d_in[9];
    const float* tb  = (const float*)d_in[10];
    const float* oW1 = (const float*)d_in[11];
    const float* ob1 = (const float*)d_in[12];
    const float* oW2 = (const float*)d_in[13];
    const float* ob2 = (const float*)d_in[14];

    float* out_logp = (float*)d_out;
    float* out_opt  = out_logp + B_TOT;
    float* out_term = out_logp + 2 * B_TOT;

    const int smem1 = 23040 * 4;   // 92,160 B
    const int smem4 = 27840 * 4;   // 111,360 B
    cudaFuncSetAttribute(trunk_kernel,  cudaFuncAttributeMaxDynamicSharedMemorySize, smem1);
    cudaFuncSetAttribute(expert_kernel, cudaFuncAttributeMaxDynamicSharedMemorySize, smem4);

    split_kernel<<<201, 256>>>(fW1, fW2, oW1, oW2, opt);
    trunk_kernel<<<B_TOT / TB, 256, smem1>>>(obs, opt, fb1, fb2,
                                             pW, pb, tW, tb, out_opt, out_term);
    scatter_kernel<<<B_TOT / 256, 256>>>(opt);
    expert_kernel<<<B_TOT / TB, 256, smem4>>>(ob1, ob2, opt, act, out_logp);
}

// round 8
// speedup vs baseline: 2.2618x; 1.0413x over previous
#include <cuda_runtime.h>
#include <cuda_bf16.h>
#include <math.h>

#define B_TOT   32768
#define OBS_DIM 256
#define HID     64
#define FEAT    128
#define N_OPT   8
#define ACT_N   18
#define TB      128

typedef unsigned long long ull;
typedef unsigned u32;

// ---------------- scratch (no allocation allowed) ----------------
__device__ u32  g_stateh[B_TOT * 64];
__device__ u32  g_statel[B_TOT * 64];
__device__ int  g_perm[B_TOT];
__device__ int  g_counts[N_OPT];
__device__ int  g_cursor[N_OPT];
// pre-split weights (packed bf16x2 along K)
__device__ u32  d_fW1h[64 * 128],  d_fW1l[64 * 128];
__device__ u32  d_fW2h[128 * 32],  d_fW2l[128 * 32];
__device__ u32  d_oW1h[8 * 64 * 64], d_oW1l[8 * 64 * 64];
__device__ u32  d_oW2h[8 * 24 * 32], d_oW2l[8 * 24 * 32];   // zero-padded 24-row image

// ---------------- helpers ----------------
__device__ __forceinline__ void cp16(u32 dst, const void* src) {
    asm volatile("cp.async.cg.shared.global [%0], [%1], 16;" :: "r"(dst), "l"(src));
}
__device__ __forceinline__ void cp_commit() {
    asm volatile("cp.async.commit_group;");
}
__device__ __forceinline__ void cp_wait_all() {
    asm volatile("cp.async.wait_group 0;" ::: "memory");
}
__device__ __forceinline__ void split2(float x, float y, u32& hi, u32& lo) {
    __nv_bfloat162 h = __floats2bfloat162_rn(x, y);
    float hx = __bfloat162float(h.x);
    float hy = __bfloat162float(h.y);
    __nv_bfloat162 l = __floats2bfloat162_rn(x - hx, y - hy);
    hi = *reinterpret_cast<u32*>(&h);
    lo = *reinterpret_cast<u32*>(&l);
}
__device__ __forceinline__ void mma16816(float d[4], const u32 a[4], const u32 b[2]) {
    asm("mma.sync.aligned.m16n8k16.row.col.f32.bf16.bf16.f32 "
        "{%0,%1,%2,%3},{%4,%5,%6,%7},{%8,%9},{%0,%1,%2,%3};"
        : "+f"(d[0]), "+f"(d[1]), "+f"(d[2]), "+f"(d[3])
        : "r"(a[0]), "r"(a[1]), "r"(a[2]), "r"(a[3]), "r"(b[0]), "r"(b[1]));
}
__device__ __forceinline__ void ldsm4(u32 r[4], u32 addr) {
    asm volatile("ldmatrix.sync.aligned.m8n8.x4.shared.b16 {%0,%1,%2,%3}, [%4];"
        : "=r"(r[0]), "=r"(r[1]), "=r"(r[2]), "=r"(r[3]) : "r"(addr));
}
__device__ __forceinline__ void ldsm2(u32 r[2], u32 addr) {
    asm volatile("ldmatrix.sync.aligned.m8n8.x2.shared.b16 {%0,%1}, [%2];"
        : "=r"(r[0]), "=r"(r[1]) : "r"(addr));
}

// Warp computes 16m x 64n of A[*][K] * W[64][K]^T (bf16x3, ldmatrix).
template <int KSTEPS>
__device__ __forceinline__ void warp_mma64(
    const u32* Ahi, const u32* Alo, int sa,
    const u32* Whi, const u32* Wlo, int sw,
    int m0, int lane, float acc[8][4])
{
    const int mat = lane >> 3, rin = lane & 7;
    u32 aOff = (u32)(((m0 + rin + ((mat & 1) << 3)) * sa + ((mat >> 1) << 2)) << 2);
    u32 aHiA = (u32)__cvta_generic_to_shared(Ahi) + aOff;
    u32 aLoA = (u32)__cvta_generic_to_shared(Alo) + aOff;
    u32 bRel = (u32)((((((mat >> 1) << 3)) + rin) * sw + ((mat & 1) << 2)) << 2);
    u32 wHiB = (u32)__cvta_generic_to_shared(Whi) + bRel;
    u32 wLoB = (u32)__cvta_generic_to_shared(Wlo) + bRel;

#pragma unroll
    for (int ks = 0; ks < KSTEPS; ks++) {
        const u32 kb = ks * 32;
        u32 ah[4], al[4];
        ldsm4(ah, aHiA + kb);
        ldsm4(al, aLoA + kb);
#pragma unroll
        for (int nb = 0; nb < 4; nb++) {
            u32 bh[4], bl[4];
            u32 off = kb + (u32)(nb * 16 * sw * 4);
            ldsm4(bh, wHiB + off);
            ldsm4(bl, wLoB + off);
            mma16816(acc[2 * nb],     ah, bh + 0);
            mma16816(acc[2 * nb + 1], ah, bh + 2);
            mma16816(acc[2 * nb],     al, bh + 0);
            mma16816(acc[2 * nb + 1], al, bh + 2);
            mma16816(acc[2 * nb],     ah, bl + 0);
            mma16816(acc[2 * nb + 1], ah, bl + 2);
        }
    }
}

// =====================================================================
// Kernel 0: pre-split weights + oW2 image + opt histogram
// =====================================================================
__global__ void split_kernel(const float* __restrict__ fW1,
                             const float* __restrict__ fW2,
                             const float* __restrict__ oW1,
                             const float* __restrict__ oW2,
                             const int* __restrict__ opt)
{
    __shared__ int s_cnt[N_OPT];
    int tid = threadIdx.x;
    if (tid < N_OPT) s_cnt[tid] = 0;
    __syncthreads();
    int i = blockIdx.x * blockDim.x + tid;
    if (i < 8192) {
        float2 v = ((const float2*)fW1)[i];
        split2(v.x, v.y, d_fW1h[i], d_fW1l[i]);
    } else if (i < 12288) {
        int k = i - 8192;
        float2 v = ((const float2*)fW2)[k];
        split2(v.x, v.y, d_fW2h[k], d_fW2l[k]);
    } else if (i < 45056) {
        int k = i - 12288;
        float2 v = ((const float2*)oW1)[k];
        split2(v.x, v.y, d_oW1h[k], d_oW1l[k]);
    } else if (i < 45056 + 8 * 24 * 32) {
        int k = i - 45056;                    // [opt][24][32]
        int o = k / 768, row = (k % 768) / 32, p = k % 32;
        u32 hi = 0, lo = 0;
        if (row < ACT_N) {
            float2 v = *(const float2*)(oW2 + (o * ACT_N + row) * HID + 2 * p);
            split2(v.x, v.y, hi, lo);
        }
        d_oW2h[k] = hi;
        d_oW2l[k] = lo;
    }
    if (i < B_TOT) atomicAdd(&s_cnt[opt[i]], 1);
    __syncthreads();
    if (tid < N_OPT && s_cnt[tid]) atomicAdd(&g_counts[tid], s_cnt[tid]);
}

// =====================================================================
// Kernel 1: trunk GEMMs (pipelined phase 1), heads, fused scatter
// smem u32 layout:
//  aHi 0..4608 | aLo 4608..9216 | w0H 9216 | w0L 11520 | w1H 13824 |
//  w1L 16128 | hHi 18432 | hLo 23040 | end 27648  (110,592 B)
//  s_pt (2048 f32) aliases aHi/aLo after phase 1
// =====================================================================
__global__ void __launch_bounds__(256, 2) trunk_kernel(
    const float* __restrict__ obs, const int* __restrict__ opt,
    const float* __restrict__ fb1, const float* __restrict__ fb2,
    const float* __restrict__ pW,  const float* __restrict__ pb,
    const float* __restrict__ tW,  const float* __restrict__ tb,
    float* __restrict__ out_opt, float* __restrict__ out_term)
{
    extern __shared__ u32 smu[];
    u32* aHi = smu;
    u32* aLo = smu + 4608;
    u32* w0H = smu + 9216;
    u32* w0L = smu + 11520;
    u32* w1H = smu + 13824;
    u32* w1L = smu + 16128;
    u32* hHi = smu + 18432;
    u32* hLo = smu + 23040;
    float* s_pt = (float*)smu;   // alias aHi/aLo after phase 1
    __shared__ int s_opt[TB];
    __shared__ int s_cnt[N_OPT];
    __shared__ int s_base[N_OPT];

    const int tid  = threadIdx.x;
    const int r0   = blockIdx.x * TB;
    const int w    = tid >> 5, lane = tid & 31;
    const int g    = lane >> 2, t = lane & 3;
    const int m0   = w * 16;
    if (tid < TB) s_opt[tid] = opt[r0 + tid];
    if (tid < N_OPT) s_cnt[tid] = 0;

    // ---------- phase 1 (pipelined): h = relu(obs @ fW1^T + fb1) ----------
    float acc[8][4];
#pragma unroll
    for (int i = 0; i < 8; i++)
#pragma unroll
        for (int j = 0; j < 4; j++) acc[i][j] = 0.f;

    // prologue: stage chunk 0 (obs -> buf0, fW1 -> w0)
#pragma unroll
    for (int it = 0; it < 2; it++) {
        int q = tid + it * 256;
        int row = q >> 3, p4 = (q & 7) << 2;
        cp16((u32)__cvta_generic_to_shared(w0H + row * 36 + p4), d_fW1h + row * 128 + p4);
        cp16((u32)__cvta_generic_to_shared(w0L + row * 36 + p4), d_fW1l + row * 128 + p4);
    }
    cp_commit();
#pragma unroll
    for (int it = 0; it < 16; it++) {
        int e = tid + it * 256;
        int row = e >> 5, p = e & 31;
        float2 ov = *(const float2*)(obs + (r0 + row) * OBS_DIM + 2 * p);
        split2(ov.x, ov.y, aHi[row * 36 + p], aLo[row * 36 + p]);
    }

#pragma unroll
    for (int kc = 0; kc < 4; kc++) {
        u32* cAhi = (kc & 1) ? hHi : aHi;
        u32* cAlo = (kc & 1) ? hLo : aLo;
        u32* cWH  = (kc & 1) ? w1H : w0H;
        u32* cWL  = (kc & 1) ? w1L : w0L;
        cp_wait_all();
        __syncthreads();
        if (kc < 3) {
            u32* nWH = (kc & 1) ? w0H : w1H;
            u32* nWL = (kc & 1) ? w0L : w1L;
#pragma unroll
            for (int it = 0; it < 2; it++) {
                int q = tid + it * 256;
                int row = q >> 3, p4 = (q & 7) << 2;
                cp16((u32)__cvta_generic_to_shared(nWH + row * 36 + p4),
                     d_fW1h + row * 128 + (kc + 1) * 32 + p4);
                cp16((u32)__cvta_generic_to_shared(nWL + row * 36 + p4),
                     d_fW1l + row * 128 + (kc + 1) * 32 + p4);
            }
            cp_commit();
            u32* nAhi = (kc & 1) ? aHi : hHi;
            u32* nAlo = (kc & 1) ? aLo : hLo;
#pragma unroll
            for (int it = 0; it < 16; it++) {
                int e = tid + it * 256;
                int row = e >> 5, p = e & 31;
                float2 ov = *(const float2*)(obs + (r0 + row) * OBS_DIM + (kc + 1) * 64 + 2 * p);
                split2(ov.x, ov.y, nAhi[row * 36 + p], nAlo[row * 36 + p]);
            }
        }
        warp_mma64<4>(cAhi, cAlo, 36, cWH, cWL, 36, m0, lane, acc);
    }
    __syncthreads();   // all MMA reads of hHi/hLo (chunk 3) done before h writes

    // epilogue -> h bf16 hi/lo
    {
        const int r1 = m0 + g, r2 = m0 + g + 8;
#pragma unroll
        for (int nt = 0; nt < 8; nt++) {
            int c = nt * 8 + 2 * t;
            float b0 = fb1[c], b1 = fb1[c + 1];
            float v0 = fmaxf(acc[nt][0] + b0, 0.f), v1 = fmaxf(acc[nt][1] + b1, 0.f);
            split2(v0, v1, hHi[r1 * 36 + (c >> 1)], hLo[r1 * 36 + (c >> 1)]);
            float v2 = fmaxf(acc[nt][2] + b0, 0.f), v3 = fmaxf(acc[nt][3] + b1, 0.f);
            split2(v2, v3, hHi[r2 * 36 + (c >> 1)], hLo[r2 * 36 + (c >> 1)]);
        }
    }

    // ---------- phase 2: state = relu(h @ fW2^T + fb2), N=128 in 2 halves ----------
    const int r1 = m0 + g, r2 = m0 + g + 8;
    const int o1 = s_opt[r1], o2 = s_opt[r2];
    float pv1 = 0.f, tv1 = 0.f, pv2 = 0.f, tv2 = 0.f;

#pragma unroll
    for (int nh = 0; nh < 2; nh++) {
#pragma unroll
        for (int it = 0; it < 2; it++) {
            int q = tid + it * 256;
            int row = q >> 3, p4 = (q & 7) << 2;
            cp16((u32)__cvta_generic_to_shared(w0H + row * 36 + p4),
                 d_fW2h + (nh * 64 + row) * 32 + p4);
            cp16((u32)__cvta_generic_to_shared(w0L + row * 36 + p4),
                 d_fW2l + (nh * 64 + row) * 32 + p4);
        }
        if (nh == 0) {
#pragma unroll
            for (int it = 0; it < 2; it++) {
                int q = tid + it * 256;
                const float* src = (q < 256) ? (pW + q * 4) : (tW + (q - 256) * 4);
                cp16((u32)__cvta_generic_to_shared(s_pt + q * 4), src);
            }
        }
        cp_commit();
        cp_wait_all();
        __syncthreads();

        float acc2[8][4];
#pragma unroll
        for (int i = 0; i < 8; i++)
#pragma unroll
            for (int j = 0; j < 4; j++) acc2[i][j] = 0.f;
        warp_mma64<4>(hHi, hLo, 36, w0H, w0L, 36, m0, lane, acc2);

#pragma unroll
        for (int nt = 0; nt < 8; nt++) {
            int c = nh * 64 + nt * 8 + 2 * t;
            float b0 = fb2[c], b1 = fb2[c + 1];
            float v0 = fmaxf(acc2[nt][0] + b0, 0.f);
            float v1 = fmaxf(acc2[nt][1] + b1, 0.f);
            float v2 = fmaxf(acc2[nt][2] + b0, 0.f);
            float v3 = fmaxf(acc2[nt][3] + b1, 0.f);
            u32 hi, lo;
            split2(v0, v1, hi, lo);
            g_stateh[(r0 + r1) * 64 + (c >> 1)] = hi;
            g_statel[(r0 + r1) * 64 + (c >> 1)] = lo;
            split2(v2, v3, hi, lo);
            g_stateh[(r0 + r2) * 64 + (c >> 1)] = hi;
            g_statel[(r0 + r2) * 64 + (c >> 1)] = lo;
            pv1 += v0 * s_pt[o1 * 128 + c] + v1 * s_pt[o1 * 128 + c + 1];
            tv1 += v0 * s_pt[1024 + o1 * 128 + c] + v1 * s_pt[1024 + o1 * 128 + c + 1];
            pv2 += v2 * s_pt[o2 * 128 + c] + v3 * s_pt[o2 * 128 + c + 1];
            tv2 += v2 * s_pt[1024 + o2 * 128 + c] + v3 * s_pt[1024 + o2 * 128 + c + 1];
        }
        __syncthreads();
    }

#pragma unroll
    for (int o = 1; o <= 2; o <<= 1) {
        pv1 += __shfl_xor_sync(0xffffffffu, pv1, o);
        tv1 += __shfl_xor_sync(0xffffffffu, tv1, o);
        pv2 += __shfl_xor_sync(0xffffffffu, pv2, o);
        tv2 += __shfl_xor_sync(0xffffffffu, tv2, o);
    }
    if (t == 0) {
        out_opt[r0 + r1]  = pv1 + pb[o1];
        out_term[r0 + r1] = 1.f / (1.f + expf(-(tv1 + tb[o1])));
        out_opt[r0 + r2]  = pv2 + pb[o2];
        out_term[r0 + r2] = 1.f / (1.f + expf(-(tv2 + tb[o2])));
    }

    // ---------- fused scatter (global histogram g_counts already complete) ----------
    int loc = 0;
    if (tid < TB) loc = atomicAdd(&s_cnt[s_opt[tid]], 1);
    __syncthreads();
    if (tid < N_OPT) {
        int base = 0;
#pragma unroll
        for (int q = 0; q < N_OPT; q++) base += (q < tid) ? g_counts[q] : 0;
        s_base[tid] = base + atomicAdd(&g_cursor[tid], s_cnt[tid]);
    }
    __syncthreads();
    if (tid < TB) g_perm[s_base[s_opt[tid]] + loc] = r0 + tid;
}

// =====================================================================
// Kernel 2: expert — MMA1 + register-fragment MMA2 logits + softmax
// =====================================================================
__global__ void __launch_bounds__(256, 2) expert_kernel(
    const float* __restrict__ ob1, const float* __restrict__ ob2,
    const int* __restrict__ opt, const int* __restrict__ act,
    float* __restrict__ out_logp)
{
    extern __shared__ u32 smu[];
    u32* stHi = smu;
    u32* stLo = smu + 8704;
    u32* wHi  = smu + 17408;
    u32* wLo  = smu + 21760;
    u32* w2h  = smu + 26112;
    u32* w2l  = smu + 26976;
    __shared__ int s_idx[TB];
    __shared__ int s_opt[TB];
    __shared__ int s_act[TB];

    const int tid  = threadIdx.x;
    const int r0   = blockIdx.x * TB;
    const int w    = tid >> 5, lane = tid & 31;
    const int g    = lane >> 2, t = lane & 3;
    const int m0   = w * 16;

    // reset sort counters for next graph replay
    if (blockIdx.x == 0 && tid < N_OPT) { g_counts[tid] = 0; g_cursor[tid] = 0; }

    if (tid < TB) {
        int gi = g_perm[r0 + tid];
        s_idx[tid] = gi;
        s_opt[tid] = opt[gi];
        s_act[tid] = act[gi];
    }
    __syncthreads();

#pragma unroll
    for (int it = 0; it < 8; it++) {
        int q = tid + it * 256;
        int row = q >> 4, p4 = (q & 15) << 2;
        int gi = s_idx[row];
        cp16((u32)__cvta_generic_to_shared(stHi + row * 68 + p4), g_stateh + gi * 64 + p4);
        cp16((u32)__cvta_generic_to_shared(stLo + row * 68 + p4), g_statel + gi * 64 + p4);
    }
    {
        int o = s_opt[0];
#pragma unroll
        for (int it = 0; it < 4; it++) {
            int q = tid + it * 256;
            int row = q >> 4, p4 = (q & 15) << 2;
            cp16((u32)__cvta_generic_to_shared(wHi + row * 68 + p4), d_oW1h + (o * 64 + row) * 64 + p4);
            cp16((u32)__cvta_generic_to_shared(wLo + row * 68 + p4), d_oW1l + (o * 64 + row) * 64 + p4);
        }
        if (tid < 192) {
            int row = tid >> 3, p4 = (tid & 7) << 2;
            cp16((u32)__cvta_generic_to_shared(w2h + row * 36 + p4), d_oW2h + o * 768 + row * 32 + p4);
            cp16((u32)__cvta_generic_to_shared(w2l + row * 36 + p4), d_oW2l + o * 768 + row * 32 + p4);
        }
    }
    cp_commit();
    cp_wait_all();
    __syncthreads();

    int j = 0;
    bool first = true;
    while (j < TB) {
        const int o = s_opt[j];
        int re = j + 1;
        while (re < TB && s_opt[re] == o) re++;

        if (!first) {
            __syncthreads();
#pragma unroll
            for (int it = 0; it < 4; it++) {
                int q = tid + it * 256;
                int row = q >> 4, p4 = (q & 15) << 2;
                cp16((u32)__cvta_generic_to_shared(wHi + row * 68 + p4), d_oW1h + (o * 64 + row) * 64 + p4);
                cp16((u32)__cvta_generic_to_shared(wLo + row * 68 + p4), d_oW1l + (o * 64 + row) * 64 + p4);
            }
            if (tid < 192) {
                int row = tid >> 3, p4 = (tid & 7) << 2;
                cp16((u32)__cvta_generic_to_shared(w2h + row * 36 + p4), d_oW2h + o * 768 + row * 32 + p4);
                cp16((u32)__cvta_generic_to_shared(w2l + row * 36 + p4), d_oW2l + o * 768 + row * 32 + p4);
            }
            cp_commit();
            cp_wait_all();
            __syncthreads();
        }
        first = false;

        // ---- MMA1 ----
        float acc[8][4];
#pragma unroll
        for (int i = 0; i < 8; i++)
#pragma unroll
            for (int q = 0; q < 4; q++) acc[i][q] = 0.f;
        warp_mma64<8>(stHi, stLo, 68, wHi, wLo, 68, m0, lane, acc);

        // ---- register epilogue -> A-fragments ----
        u32 ah1[8], al1[8], ah2[8], al2[8];
#pragma unroll
        for (int nt = 0; nt < 8; nt++) {
            int c = nt * 8 + 2 * t;
            float b0 = ob1[o * HID + c], b1 = ob1[o * HID + c + 1];
            split2(fmaxf(acc[nt][0] + b0, 0.f), fmaxf(acc[nt][1] + b1, 0.f), ah1[nt], al1[nt]);
            split2(fmaxf(acc[nt][2] + b0, 0.f), fmaxf(acc[nt][3] + b1, 0.f), ah2[nt], al2[nt]);
        }

        // ---- MMA2: logits ----
        float accL[3][4];
#pragma unroll
        for (int i = 0; i < 3; i++)
#pragma unroll
            for (int q = 0; q < 4; q++) accL[i][q] = 0.f;
        {
            const int mat = lane >> 3, rin = lane & 7;
            u32 b4h = (u32)__cvta_generic_to_shared(w2h) +
                      (u32)(((((mat >> 1) << 3) + rin) * 36 + ((mat & 1) << 2)) << 2);
            u32 b4l = (u32)__cvta_generic_to_shared(w2l) +
                      (u32)(((((mat >> 1) << 3) + rin) * 36 + ((mat & 1) << 2)) << 2);
            const int l16 = lane & 15;
            u32 b2off = (u32)(((16 + (l16 & 7)) * 36 + (((l16 >> 3) & 1) << 2)) << 2);
            u32 b2h = (u32)__cvta_generic_to_shared(w2h) + b2off;
            u32 b2l = (u32)__cvta_generic_to_shared(w2l) + b2off;
#pragma unroll
            for (int ks = 0; ks < 4; ks++) {
                u32 kb = ks * 32;
                u32 ah[4] = { ah1[2 * ks], ah2[2 * ks], ah1[2 * ks + 1], ah2[2 * ks + 1] };
                u32 al[4] = { al1[2 * ks], al2[2 * ks], al1[2 * ks + 1], al2[2 * ks + 1] };
                u32 bh[4], bl[4], bh2[2], bl2[2];
                ldsm4(bh, b4h + kb);
                ldsm4(bl, b4l + kb);
                ldsm2(bh2, b2h + kb);
                ldsm2(bl2, b2l + kb);
                mma16816(accL[0], ah, bh + 0);
                mma16816(accL[1], ah, bh + 2);
                mma16816(accL[2], ah, bh2);
                mma16816(accL[0], al, bh + 0);
                mma16816(accL[1], al, bh + 2);
                mma16816(accL[2], al, bh2);
                mma16816(accL[0], ah, bl + 0);
                mma16816(accL[1], ah, bl + 2);
                mma16816(accL[2], ah, bl2);
            }
        }

        // ---- softmax on fragments ----
#pragma unroll
        for (int half = 0; half < 2; half++) {
            int rr = m0 + g + half * 8;
            float v[3][2];
#pragma unroll
            for (int nt = 0; nt < 3; nt++)
#pragma unroll
                for (int i = 0; i < 2; i++) {
                    int c = nt * 8 + 2 * t + i;
                    v[nt][i] = (c < ACT_N) ? accL[nt][half * 2 + i] + ob2[o * ACT_N + c]
                                           : -INFINITY;
                }
            float m = v[0][0];
#pragma unroll
            for (int nt = 0; nt < 3; nt++)
#pragma unroll
                for (int i = 0; i < 2; i++) m = fmaxf(m, v[nt][i]);
            m = fmaxf(m, __shfl_xor_sync(0xffffffffu, m, 1));
            m = fmaxf(m, __shfl_xor_sync(0xffffffffu, m, 2));
            float S = 0.f;
#pragma unroll
            for (int nt = 0; nt < 3; nt++)
#pragma unroll
                for (int i = 0; i < 2; i++) S += expf(v[nt][i] - m);
            S += __shfl_xor_sync(0xffffffffu, S, 1);
            S += __shfl_xor_sync(0xffffffffu, S, 2);
            int a = s_act[rr];
            float cand = 0.f;
#pragma unroll
            for (int nt = 0; nt < 3; nt++)
#pragma unroll
                for (int i = 0; i < 2; i++) {
                    int c = nt * 8 + 2 * t + i;
                    cand = (c == a) ? v[nt][i] : cand;
                }
            cand += __shfl_xor_sync(0xffffffffu, cand, 1);
            cand += __shfl_xor_sync(0xffffffffu, cand, 2);
            if (t == 0 && rr >= j && rr < re)
                out_logp[s_idx[rr]] = cand - m - logf(S);
        }
        j = re;
    }
}

// =====================================================================
extern "C" void kernel_launch(void* const* d_in, const int* in_sizes, int n_in,
                              void* d_out, int out_size)
{
    const float* obs = (const float*)d_in[0];
    const int*   act = (const int*)  d_in[1];
    const int*   opt = (const int*)  d_in[2];
    const float* fW1 = (const float*)d_in[3];
    const float* fb1 = (const float*)d_in[4];
    const float* fW2 = (const float*)d_in[5];
    const float* fb2 = (const float*)d_in[6];
    const float* pW  = (const float*)d_in[7];
    const float* pb  = (const float*)d_in[8];
    const float* tW  = (const float*)d_in[9];
    const float* tb  = (const float*)d_in[10];
    const float* oW1 = (const float*)d_in[11];
    const float* ob1 = (const float*)d_in[12];
    const float* oW2 = (const float*)d_in[13];
    const float* ob2 = (const float*)d_in[14];

    float* out_logp = (float*)d_out;
    float* out_opt  = out_logp + B_TOT;
    float* out_term = out_logp + 2 * B_TOT;

    const int smem1 = 27648 * 4;   // 110,592 B
    const int smem4 = 27840 * 4;   // 111,360 B
    cudaFuncSetAttribute(trunk_kernel,  cudaFuncAttributeMaxDynamicSharedMemorySize, smem1);
    cudaFuncSetAttribute(expert_kernel, cudaFuncAttributeMaxDynamicSharedMemorySize, smem4);

    split_kernel<<<201, 256>>>(fW1, fW2, oW1, oW2, opt);
    trunk_kernel<<<B_TOT / TB, 256, smem1>>>(obs, opt, fb1, fb2,
                                             pW, pb, tW, tb, out_opt, out_term);
    expert_kernel<<<B_TOT / TB, 256, smem4>>>(ob1, ob2, opt, act, out_logp);
}